// round 9
// baseline (speedup 1.0000x reference)
#include <cuda_runtime.h>
#include <math.h>

#define N        96
#define NB       8       // one cluster of 8 CTAs; CTA b owns rows 12b..12b+11
#define NT       384     // 12 warps
#define RPB      12      // rows per block
#define NN       9216
#define IN_DIM   64
#define HID      256
#define ZD       64
#define E        1024
#define NUM_LOGITS 4656
#define ITERS    50
#define UTRI     4560
#define DMAX     32      // padded neighbor-list capacity

// ---------------- device scratch (no allocations allowed) ----------------
__device__ float g_Anorm[NN];
__device__ float g_T[N * HID];
__device__ float g_P[N * HID];
__device__ float g_H[N * HID];
__device__ float g_gv[HID];
__device__ float g_B[NN];
__device__ float g_degA[N];
__device__ int   g_deg[N];
__device__ int   g_nbr[NN];
__device__ float g_M[2][NN + N];      // +1 zero row for padded neighbors
__device__ float g_part[2][NB];       // per-CTA sum-of-squares partials

// Cluster-wide barrier (~380 cyc), release/acquire across the cluster.
#define CSYNC() do { \
    asm volatile("barrier.cluster.arrive.aligned;" ::: "memory"); \
    asm volatile("barrier.cluster.wait.aligned;"   ::: "memory"); \
} while (0)

__global__ void __launch_bounds__(NT, 1) __cluster_dims__(NB, 1, 1)
fused_graphvae(
    const float* __restrict__ x,   const int* __restrict__ ei,
    const float* __restrict__ adj,
    const float* __restrict__ W1,  const float* __restrict__ g1,  const float* __restrict__ be1,
    const float* __restrict__ W2,  const float* __restrict__ g2,  const float* __restrict__ be2,
    const float* __restrict__ Wmu, const float* __restrict__ bmu,
    const float* __restrict__ Wlv, const float* __restrict__ blv,
    const float* __restrict__ Wd1, const float* __restrict__ bd1,
    const float* __restrict__ Wd2, const float* __restrict__ bd2,
    const float* __restrict__ eps, float* __restrict__ out)
{
    __shared__ float dyn[NN];                       // 36 KB staging / B'
    __shared__ __align__(16) float sX[RPB * N];     // this CTA's 12 X rows
    __shared__ float sND[RPB * N];                  // nd rows
    __shared__ int   snbroff[RPB * DMAX];           // padded nbr word-offsets
    __shared__ int   sdegp[RPB];                    // padded degrees (mult of 4)
    __shared__ float sdb[N];                        // degB per column (prep)
    __shared__ float red[12];

    const int t    = threadIdx.x;          // 0..383
    const int bid  = blockIdx.x;           // 0..7
    const int lane = t & 31, wid = t >> 5;
    const int kk   = t % 96;               // X-update column
    const int row0 = t / 96;               // 0..3
    const int q    = t >> 2;               // M-compute: k column 0..95
    const int c    = t & 3;                // M-compute: l-quarter 0..3

    // ============ Ph1: adjacency (CTA 0) + gemm1 (CTAs 1..7) ===============
    if (bid == 0) {
        for (int i = t; i < NN; i += NT) dyn[i] = 0.f;
        __syncthreads();
        for (int e = t; e < E; e += NT)
            dyn[ei[e] * N + ei[E + e]] = 1.f;      // identical-value races OK
        __syncthreads();
        if (t < N) dyn[t * (N + 1)] = 1.f;         // A = max(A, I)
        __syncthreads();
        for (int rr = wid; rr < N; rr += 12) {     // warp-per-row sums
            float s = dyn[rr * N + lane] + dyn[rr * N + lane + 32]
                    + dyn[rr * N + lane + 64];
            #pragma unroll
            for (int o = 16; o; o >>= 1) s += __shfl_xor_sync(~0u, s, o);
            if (lane == 0) sX[rr] = rsqrtf(s);     // sX as temp dinv
        }
        __syncthreads();
        for (int i = t; i < NN; i += NT) {
            int rr = i / N, cc = i - rr * N;
            __stcg(&g_Anorm[i], dyn[i] * sX[rr] * sX[cc]);
        }
        if (t < N) {
            float s = 0.f; int cnt = 0;
            for (int j = 0; j < N; j++) {
                float v = adj[t * N + j];
                s += v;
                if (v > 0.5f) __stcg(&g_nbr[t * N + cnt++], j);
            }
            __stcg(&g_degA[t], s + 1.f);           // Agt diag forced to 1
            __stcg(&g_deg[t], cnt);
        }
    } else {
        // T = x @ W1 (bias b1 exactly cancelled by BN); float4 over columns
        for (int e = t; e < N * IN_DIM; e += NT) dyn[e] = x[e];
        __syncthreads();
        for (int qq = (bid - 1) * NT + t; qq < N * (HID / 4); qq += 7 * NT) {
            int i = qq >> 6, c4 = (qq & 63) << 2;
            float a0 = 0, a1 = 0, a2 = 0, a3 = 0;
            #pragma unroll
            for (int k2 = 0; k2 < IN_DIM; k2++) {
                float xv = dyn[i * IN_DIM + k2];
                float4 w = *(const float4*)&W1[k2 * HID + c4];
                a0 += xv * w.x; a1 += xv * w.y; a2 += xv * w.z; a3 += xv * w.w;
            }
            __stcg((float4*)&g_T[i * HID + c4], make_float4(a0, a1, a2, a3));
        }
    }
    CSYNC();

    // ============ gcn: P = A_norm @ T (12 rows per CTA) =====================
    auto gcn = [&]() {
        for (int e = t; e < RPB * N; e += NT)
            dyn[e] = __ldcg(&g_Anorm[bid * RPB * N + e]);
        __syncthreads();
        for (int qq = t; qq < RPB * (HID / 4); qq += NT) {
            int rr = qq >> 6, c4 = (qq & 63) << 2;
            float a0 = 0, a1 = 0, a2 = 0, a3 = 0;
            #pragma unroll 4
            for (int j = 0; j < N; j++) {
                float av = dyn[rr * N + j];
                float4 tv = __ldcg((const float4*)&g_T[j * HID + c4]);
                a0 += av * tv.x; a1 += av * tv.y; a2 += av * tv.z; a3 += av * tv.w;
            }
            __stcg((float4*)&g_P[(bid * RPB + rr) * HID + c4],
                   make_float4(a0, a1, a2, a3));
        }
    };
    // ============ bn: BN + relu, warp-per-column (32 cols per CTA) ==========
    auto bn = [&](const float* gamma, const float* beta, int write_h, int do_gv) {
        for (int cc = wid; cc < 32; cc += 12) {
            int col = bid * 32 + cc;
            float v0 = __ldcg(&g_P[lane * HID + col]);
            float v1 = __ldcg(&g_P[(lane + 32) * HID + col]);
            float v2 = __ldcg(&g_P[(lane + 64) * HID + col]);
            float s = v0 + v1 + v2;
            float qd = v0 * v0 + v1 * v1 + v2 * v2;
            #pragma unroll
            for (int o = 16; o; o >>= 1) {
                s  += __shfl_xor_sync(~0u, s, o);
                qd += __shfl_xor_sync(~0u, qd, o);
            }
            float m   = s * (1.f / N);
            float var = qd * (1.f / N) - m * m;
            float inv = rsqrtf(var + 1e-5f) * gamma[col];
            float bb  = beta[col];
            float h0 = fmaxf((v0 - m) * inv + bb, 0.f);
            float h1 = fmaxf((v1 - m) * inv + bb, 0.f);
            float h2 = fmaxf((v2 - m) * inv + bb, 0.f);
            if (write_h) {
                __stcg(&g_H[lane * HID + col], h0);
                __stcg(&g_H[(lane + 32) * HID + col], h1);
                __stcg(&g_H[(lane + 64) * HID + col], h2);
            }
            if (do_gv) {
                float gs = h0 + h1 + h2;
                #pragma unroll
                for (int o = 16; o; o >>= 1) gs += __shfl_xor_sync(~0u, gs, o);
                if (lane == 0) __stcg(&g_gv[col], gs * (1.f / N));
            }
        }
    };

    gcn();             CSYNC();
    bn(g1, be1, 1, 0); CSYNC();

    // ============ gemm2: T = H @ W2 =========================================
    {
        for (int e = t; e < RPB * HID; e += NT)
            dyn[e] = __ldcg(&g_H[bid * RPB * HID + e]);
        __syncthreads();
        for (int qq = t; qq < RPB * (HID / 4); qq += NT) {
            int rr = qq >> 6, c4 = (qq & 63) << 2;
            float a0 = 0, a1 = 0, a2 = 0, a3 = 0;
            #pragma unroll 4
            for (int k2 = 0; k2 < HID; k2++) {
                float hv = dyn[rr * HID + k2];
                float4 w = *(const float4*)&W2[k2 * HID + c4];
                a0 += hv * w.x; a1 += hv * w.y; a2 += hv * w.z; a3 += hv * w.w;
            }
            __stcg((float4*)&g_T[(bid * RPB + rr) * HID + c4],
                   make_float4(a0, a1, a2, a3));
        }
    }
    CSYNC();
    gcn();             CSYNC();
    bn(g2, be2, 0, 1); CSYNC();          // bn2: only g_vec needed

    // ============ head (replicated per CTA) + decoder -> B ==================
    {
        if (t < HID) dyn[t] = __ldcg(&g_gv[t]);
        __syncthreads();
        if (t < ZD) {
            float mu = bmu[t], lv = blv[t];
            #pragma unroll 4
            for (int k2 = 0; k2 < HID; k2++) {
                float g = dyn[k2];
                mu += g * Wmu[k2 * ZD + t];
                lv += g * Wlv[k2 * ZD + t];
            }
            lv = fminf(fmaxf(lv, -4.f), 4.f);
            dyn[HID + t] = mu + eps[t] * expf(0.5f * lv);
        }
        __syncthreads();
        if (t < HID) {
            float a = bd1[t];
            #pragma unroll
            for (int d = 0; d < ZD; d++) a += dyn[HID + d] * Wd1[d * HID + t];
            dyn[HID + ZD + t] = fmaxf(a, 0.f);     // d1
        }
        __syncthreads();
        for (int u = bid * NT + t; u < UTRI; u += NB * NT) {
            int uu = u, rr = 0, rem = N - 1;
            while (uu >= rem) { uu -= rem; rem--; rr++; }
            int cc = rr + 1 + uu;
            float a = bd2[u];
            #pragma unroll 4
            for (int k2 = 0; k2 < HID; k2++)
                a += dyn[HID + ZD + k2] * Wd2[k2 * NUM_LOGITS + u];
            float th  = tanhf(a);
            float sig = 1.f / (1.f + expf(-th));
            __stcg(&g_B[rr * N + cc], sig);
            __stcg(&g_B[cc * N + rr], sig);
        }
        if (bid == 0 && t < N) __stcg(&g_B[t * (N + 1)], 1.f);   // diag = 1
    }
    CSYNC();

    // ============ prep: B' (diag zeroed), nd, X0, M0, nbr offsets ===========
    {
        for (int i = t; i < NN; i += NT) {
            int rr = i / N, cc = i - rr * N;
            dyn[i] = (rr == cc) ? 0.f : __ldcg(&g_B[i]);
        }
        __syncthreads();
        if (t < N) {                  // column stats (B symmetric): conflict-free
            float db = 1.f, mx = 0.f;
            #pragma unroll 4
            for (int l = 0; l < N; l++) {
                float b = dyn[l * N + t];
                db += b;
                mx = fmaxf(mx, b);
            }
            sdb[t] = db;
            float m0 = mx * (1.f / N);            // X0 uniform, ||X0||_F = 1
            for (int r2 = 0; r2 < RPB; r2++)
                __stcg(&g_M[0][(bid * RPB + r2) * N + t], m0);
            // zero row for padded neighbor loads (both buffers)
            if (bid == 0) { __stcg(&g_M[0][NN + t], 0.f); __stcg(&g_M[1][NN + t], 0.f); }
        }
        __syncthreads();
        #pragma unroll
        for (int i2 = 0; i2 < 3; i2++) {
            int e  = t + i2 * NT;
            int rw = row0 + i2 * 4;
            sND[e] = 1.f / (fabsf(__ldcg(&g_degA[bid * RPB + rw]) - sdb[kk]) + 1.f);
            sX[e]  = 1.f / N;
        }
        // padded neighbor word-offsets: NT == RPB*DMAX exactly
        {
            int rw = t / DMAX, m = t % DMAX;
            int dg = __ldcg(&g_deg[bid * RPB + rw]);
            dg = (dg > DMAX) ? DMAX : dg;
            snbroff[t] = (m < dg) ? __ldcg(&g_nbr[(bid * RPB + rw) * N + m]) * N
                                  : NN;            // points at the zero row
            if (m == 0) sdegp[rw] = (dg + 3) & ~3;
        }
    }
    __syncthreads();
    // Cache this thread's 24 B' column values in registers for all 50 iters.
    float Breg[24];
    #pragma unroll
    for (int j = 0; j < 24; j++) Breg[j] = dyn[(24 * c + j) * N + q];
    CSYNC();

    // ============ 50 MPM iterations, one cluster.sync each ==================
    // F positively homogeneous: exact norm carried as scalar; partials
    // published in the same release (CSYNC) as the M rows.
    const int gbase = bid * RPB * N;
    for (int it = 0; it < ITERS; it++) {
        const float* __restrict__ Min  = g_M[it & 1];
        float*       __restrict__ Mout = g_M[(it + 1) & 1];

        // scale computed redundantly per warp: no block sync needed for it
        float scale;
        if (it == 0) scale = 1.f;
        else {
            float p = (lane < NB) ? __ldcg(&g_part[(it - 1) & 1][lane]) : 0.f;
            p += __shfl_xor_sync(~0u, p, 4);
            p += __shfl_xor_sync(~0u, p, 2);
            p += __shfl_xor_sync(~0u, p, 1);
            scale = rsqrtf(__shfl_sync(~0u, p, 0));
        }

        // X update: raw = x*nd + sum of neighbor M rows (batched LDGs)
        float a[3];
        #pragma unroll
        for (int i2 = 0; i2 < 3; i2++) {
            int e   = t + i2 * NT;
            int rw  = row0 + i2 * 4;
            float raw = sX[e] * sND[e];
            int dp = sdegp[rw];
            const int* off = &snbroff[rw * DMAX];
            for (int m = 0; m < dp; m += 4) {
                int o0 = off[m], o1 = off[m + 1], o2 = off[m + 2], o3 = off[m + 3];
                raw += __ldcg(&Min[o0 + kk]) + __ldcg(&Min[o1 + kk])
                     + __ldcg(&Min[o2 + kk]) + __ldcg(&Min[o3 + kk]);
            }
            a[i2] = raw;
        }
        float sq = 0.f;
        #pragma unroll
        for (int i2 = 0; i2 < 3; i2++) {
            float v = a[i2] * scale;
            sX[t + i2 * NT] = v;
            sq += v * v;
        }
        #pragma unroll
        for (int o = 16; o; o >>= 1) sq += __shfl_xor_sync(~0u, sq, o);
        if (lane == 0) red[wid] = sq;
        __syncthreads();                 // publishes new sX + red
        if (t == 0) {
            float s2 = 0.f;
            #pragma unroll
            for (int w = 0; w < 12; w++) s2 += red[w];
            __stcg(&g_part[it & 1][bid], s2);
        }

        if (it != ITERS - 1) {
            // M[row,k] = max_{l!=k} B'[l,k] * x_row[l]
            // thread (k=q, quarter c): 24 l's from registers, float4 x loads.
            for (int r2 = 0; r2 < RPB; r2++) {
                const float4* xp = (const float4*)&sX[r2 * N + 24 * c];
                float ma = 0.f, mb = 0.f;
                #pragma unroll
                for (int j = 0; j < 6; j++) {
                    float4 xv = xp[j];
                    ma = fmaxf(ma, Breg[4 * j + 0] * xv.x);
                    mb = fmaxf(mb, Breg[4 * j + 1] * xv.y);
                    ma = fmaxf(ma, Breg[4 * j + 2] * xv.z);
                    mb = fmaxf(mb, Breg[4 * j + 3] * xv.w);
                }
                float m = fmaxf(ma, mb);
                m = fmaxf(m, __shfl_down_sync(~0u, m, 1));
                m = fmaxf(m, __shfl_down_sync(~0u, m, 2));
                if (c == 0) __stcg(&Mout[gbase + r2 * N + q], m);
            }
        }
        CSYNC();
    }

    // ============ final normalize + write ===================================
    {
        float p = (lane < NB) ? __ldcg(&g_part[(ITERS - 1) & 1][lane]) : 0.f;
        p += __shfl_xor_sync(~0u, p, 4);
        p += __shfl_xor_sync(~0u, p, 2);
        p += __shfl_xor_sync(~0u, p, 1);
        float os = rsqrtf(__shfl_sync(~0u, p, 0));
        #pragma unroll
        for (int i2 = 0; i2 < 3; i2++)
            out[gbase + t + i2 * NT] = sX[t + i2 * NT] * os;
    }
}

// ---------------- launch ----------------
extern "C" void kernel_launch(void* const* d_in, const int* in_sizes, int n_in,
                              void* d_out, int out_size) {
    const float* x   = (const float*)d_in[0];
    const int*   ei  = (const int*)  d_in[1];
    const float* adj = (const float*)d_in[2];
    const float* W1  = (const float*)d_in[3];
    // d_in[4] = b1 (cancelled by BN)
    const float* g1  = (const float*)d_in[5];
    const float* be1 = (const float*)d_in[6];
    const float* W2  = (const float*)d_in[7];
    // d_in[8] = b2 (cancelled by BN)
    const float* g2  = (const float*)d_in[9];
    const float* be2 = (const float*)d_in[10];
    const float* Wmu = (const float*)d_in[11];
    const float* bmu = (const float*)d_in[12];
    const float* Wlv = (const float*)d_in[13];
    const float* blv = (const float*)d_in[14];
    const float* Wd1 = (const float*)d_in[15];
    const float* bd1 = (const float*)d_in[16];
    const float* Wd2 = (const float*)d_in[17];
    const float* bd2 = (const float*)d_in[18];
    const float* eps = (const float*)d_in[19];

    fused_graphvae<<<NB, NT>>>(
        x, ei, adj, W1, g1, be1, W2, g2, be2,
        Wmu, bmu, Wlv, blv, Wd1, bd1, Wd2, bd2, eps, (float*)d_out);
}

// round 10
// speedup vs baseline: 1.4537x; 1.4537x over previous
#include <cuda_runtime.h>
#include <math.h>

#define N        96
#define NT       384     // 12 warps per CTA
#define NN       9216
#define IN_DIM   64
#define HID      256
#define ZD       64
#define E        1024
#define NUM_LOGITS 4656
#define ITERS    50
#define UTRI     4560
#define DMAX     32      // padded neighbor-list capacity

// ---------------- device scratch (no allocations allowed) ----------------
__device__ float g_Anorm[NN];
__device__ float g_T[N * HID];
__device__ float g_P[N * HID];
__device__ float g_H[N * HID];
__device__ float g_gv[HID];
__device__ float g_B[NN];
__device__ float g_degA[N];
__device__ int   g_deg[N];
__device__ int   g_nbr[NN];
__device__ float g_M[2][NN + N];      // +1 zero row for padded neighbors
__device__ float g_part[2][16];       // per-CTA sum-of-squares partials

// Cluster-wide barrier (~380 cyc), release/acquire across the cluster.
#define CSYNC() do { \
    asm volatile("barrier.cluster.arrive.aligned;" ::: "memory"); \
    asm volatile("barrier.cluster.wait.aligned;"   ::: "memory"); \
} while (0)

template <int CSZ>
__global__ void __launch_bounds__(NT, 1)
fused_graphvae(
    const float* __restrict__ x,   const int* __restrict__ ei,
    const float* __restrict__ adj,
    const float* __restrict__ W1,  const float* __restrict__ g1,  const float* __restrict__ be1,
    const float* __restrict__ W2,  const float* __restrict__ g2,  const float* __restrict__ be2,
    const float* __restrict__ Wmu, const float* __restrict__ bmu,
    const float* __restrict__ Wlv, const float* __restrict__ blv,
    const float* __restrict__ Wd1, const float* __restrict__ bd1,
    const float* __restrict__ Wd2, const float* __restrict__ bd2,
    const float* __restrict__ eps, float* __restrict__ out)
{
    constexpr int RPB = N / CSZ;                    // rows per CTA (12 or 6)
    constexpr int CPC = HID / CSZ;                  // BN columns per CTA

    __shared__ float dyn[NN];                       // 36 KB staging / B'
    __shared__ __align__(16) float sX[RPB * N];     // this CTA's X rows
    __shared__ float sND[RPB * N];                  // nd rows
    __shared__ int   snbroff[RPB * DMAX];           // padded nbr word-offsets
    __shared__ int   sdegp[RPB];                    // padded degrees (mult of 4)
    __shared__ float sdb[N];                        // degB per column (prep)
    __shared__ float red[12];

    const int t    = threadIdx.x;          // 0..383
    const int bid  = blockIdx.x;           // 0..CSZ-1
    const int lane = t & 31, wid = t >> 5;
    const int kk   = t % 96;               // X-update column (384 % 96 == 0)
    const int row0 = t / 96;               // 0..3
    const int q    = t >> 2;               // M-compute: k column 0..95
    const int c    = t & 3;                // M-compute: l-quarter 0..3

    // ============ Ph1: adjacency (CTA 0) + gemm1 (others) ==================
    if (bid == 0) {
        for (int i = t; i < NN; i += NT) dyn[i] = 0.f;
        __syncthreads();
        for (int e = t; e < E; e += NT)
            dyn[ei[e] * N + ei[E + e]] = 1.f;      // identical-value races OK
        __syncthreads();
        if (t < N) dyn[t * (N + 1)] = 1.f;         // A = max(A, I)
        __syncthreads();
        for (int rr = wid; rr < N; rr += 12) {     // warp-per-row sums
            float s = dyn[rr * N + lane] + dyn[rr * N + lane + 32]
                    + dyn[rr * N + lane + 64];
            #pragma unroll
            for (int o = 16; o; o >>= 1) s += __shfl_xor_sync(~0u, s, o);
            if (lane == 0) sX[rr] = rsqrtf(s);     // sX as temp dinv
        }
        __syncthreads();
        for (int i = t; i < NN; i += NT) {
            int rr = i / N, cc = i - rr * N;
            __stcg(&g_Anorm[i], dyn[i] * sX[rr] * sX[cc]);
        }
        if (t < N) {
            float s = 0.f; int cnt = 0;
            for (int j = 0; j < N; j++) {
                float v = adj[t * N + j];
                s += v;
                if (v > 0.5f) __stcg(&g_nbr[t * N + cnt++], j);
            }
            __stcg(&g_degA[t], s + 1.f);           // Agt diag forced to 1
            __stcg(&g_deg[t], cnt);
        }
    } else {
        // T = x @ W1 (bias b1 exactly cancelled by BN); float4 over columns
        for (int e = t; e < N * IN_DIM; e += NT) dyn[e] = x[e];
        __syncthreads();
        for (int qq = (bid - 1) * NT + t; qq < N * (HID / 4); qq += (CSZ - 1) * NT) {
            int i = qq >> 6, c4 = (qq & 63) << 2;
            float a0 = 0, a1 = 0, a2 = 0, a3 = 0;
            #pragma unroll
            for (int k2 = 0; k2 < IN_DIM; k2++) {
                float xv = dyn[i * IN_DIM + k2];
                float4 w = *(const float4*)&W1[k2 * HID + c4];
                a0 += xv * w.x; a1 += xv * w.y; a2 += xv * w.z; a3 += xv * w.w;
            }
            __stcg((float4*)&g_T[i * HID + c4], make_float4(a0, a1, a2, a3));
        }
    }
    CSYNC();

    // ============ gcn: P = A_norm @ T (RPB rows per CTA) ====================
    auto gcn = [&]() {
        for (int e = t; e < RPB * N; e += NT)
            dyn[e] = __ldcg(&g_Anorm[bid * RPB * N + e]);
        __syncthreads();
        for (int qq = t; qq < RPB * (HID / 4); qq += NT) {
            int rr = qq >> 6, c4 = (qq & 63) << 2;
            float a0 = 0, a1 = 0, a2 = 0, a3 = 0;
            #pragma unroll 4
            for (int j = 0; j < N; j++) {
                float av = dyn[rr * N + j];
                float4 tv = __ldcg((const float4*)&g_T[j * HID + c4]);
                a0 += av * tv.x; a1 += av * tv.y; a2 += av * tv.z; a3 += av * tv.w;
            }
            __stcg((float4*)&g_P[(bid * RPB + rr) * HID + c4],
                   make_float4(a0, a1, a2, a3));
        }
    };
    // ============ bn: BN + relu, warp-per-column ============================
    auto bn = [&](const float* gamma, const float* beta, int write_h, int do_gv) {
        for (int cc = wid; cc < CPC; cc += 12) {
            int col = bid * CPC + cc;
            float v0 = __ldcg(&g_P[lane * HID + col]);
            float v1 = __ldcg(&g_P[(lane + 32) * HID + col]);
            float v2 = __ldcg(&g_P[(lane + 64) * HID + col]);
            float s = v0 + v1 + v2;
            float qd = v0 * v0 + v1 * v1 + v2 * v2;
            #pragma unroll
            for (int o = 16; o; o >>= 1) {
                s  += __shfl_xor_sync(~0u, s, o);
                qd += __shfl_xor_sync(~0u, qd, o);
            }
            float m   = s * (1.f / N);
            float var = qd * (1.f / N) - m * m;
            float inv = rsqrtf(var + 1e-5f) * gamma[col];
            float bb  = beta[col];
            float h0 = fmaxf((v0 - m) * inv + bb, 0.f);
            float h1 = fmaxf((v1 - m) * inv + bb, 0.f);
            float h2 = fmaxf((v2 - m) * inv + bb, 0.f);
            if (write_h) {
                __stcg(&g_H[lane * HID + col], h0);
                __stcg(&g_H[(lane + 32) * HID + col], h1);
                __stcg(&g_H[(lane + 64) * HID + col], h2);
            }
            if (do_gv) {
                float gs = h0 + h1 + h2;
                #pragma unroll
                for (int o = 16; o; o >>= 1) gs += __shfl_xor_sync(~0u, gs, o);
                if (lane == 0) __stcg(&g_gv[col], gs * (1.f / N));
            }
        }
    };

    gcn();             CSYNC();
    bn(g1, be1, 1, 0); CSYNC();

    // ============ gemm2: T = H @ W2 =========================================
    {
        for (int e = t; e < RPB * HID; e += NT)
            dyn[e] = __ldcg(&g_H[bid * RPB * HID + e]);
        __syncthreads();
        for (int qq = t; qq < RPB * (HID / 4); qq += NT) {
            int rr = qq >> 6, c4 = (qq & 63) << 2;
            float a0 = 0, a1 = 0, a2 = 0, a3 = 0;
            #pragma unroll 4
            for (int k2 = 0; k2 < HID; k2++) {
                float hv = dyn[rr * HID + k2];
                float4 w = *(const float4*)&W2[k2 * HID + c4];
                a0 += hv * w.x; a1 += hv * w.y; a2 += hv * w.z; a3 += hv * w.w;
            }
            __stcg((float4*)&g_T[(bid * RPB + rr) * HID + c4],
                   make_float4(a0, a1, a2, a3));
        }
    }
    CSYNC();
    gcn();             CSYNC();
    bn(g2, be2, 0, 1); CSYNC();          // bn2: only g_vec needed

    // ============ head (replicated per CTA) + decoder -> B ==================
    {
        if (t < HID) dyn[t] = __ldcg(&g_gv[t]);
        __syncthreads();
        if (t < ZD) {
            float mu = bmu[t], lv = blv[t];
            #pragma unroll 4
            for (int k2 = 0; k2 < HID; k2++) {
                float g = dyn[k2];
                mu += g * Wmu[k2 * ZD + t];
                lv += g * Wlv[k2 * ZD + t];
            }
            lv = fminf(fmaxf(lv, -4.f), 4.f);
            dyn[HID + t] = mu + eps[t] * expf(0.5f * lv);
        }
        __syncthreads();
        if (t < HID) {
            float a = bd1[t];
            #pragma unroll
            for (int d = 0; d < ZD; d++) a += dyn[HID + d] * Wd1[d * HID + t];
            dyn[HID + ZD + t] = fmaxf(a, 0.f);     // d1
        }
        __syncthreads();
        for (int u = bid * NT + t; u < UTRI; u += CSZ * NT) {
            int uu = u, rr = 0, rem = N - 1;
            while (uu >= rem) { uu -= rem; rem--; rr++; }
            int cc = rr + 1 + uu;
            float a = bd2[u];
            #pragma unroll 4
            for (int k2 = 0; k2 < HID; k2++)
                a += dyn[HID + ZD + k2] * Wd2[k2 * NUM_LOGITS + u];
            float th  = tanhf(a);
            float sig = 1.f / (1.f + expf(-th));
            __stcg(&g_B[rr * N + cc], sig);
            __stcg(&g_B[cc * N + rr], sig);
        }
        if (bid == 0 && t < N) __stcg(&g_B[t * (N + 1)], 1.f);   // diag = 1
    }
    CSYNC();

    // ============ prep: B' (diag zeroed), nd, X0, M0, nbr offsets ===========
    {
        for (int i = t; i < NN; i += NT) {
            int rr = i / N, cc = i - rr * N;
            dyn[i] = (rr == cc) ? 0.f : __ldcg(&g_B[i]);
        }
        __syncthreads();
        if (t < N) {                  // column stats (B symmetric): conflict-free
            float db = 1.f, mx = 0.f;
            #pragma unroll 4
            for (int l = 0; l < N; l++) {
                float b = dyn[l * N + t];
                db += b;
                mx = fmaxf(mx, b);
            }
            sdb[t] = db;
            float m0 = mx * (1.f / N);            // X0 uniform, ||X0||_F = 1
            for (int r2 = 0; r2 < RPB; r2++)
                __stcg(&g_M[0][(bid * RPB + r2) * N + t], m0);
            // zero row for padded neighbor loads (both buffers)
            if (bid == 0) { __stcg(&g_M[0][NN + t], 0.f); __stcg(&g_M[1][NN + t], 0.f); }
        }
        __syncthreads();
        for (int e = t; e < RPB * N; e += NT) {
            int rw = e / 96;
            sND[e] = 1.f / (fabsf(__ldcg(&g_degA[bid * RPB + rw]) - sdb[kk]) + 1.f);
            sX[e]  = 1.f / N;
        }
        for (int e = t; e < RPB * DMAX; e += NT) {
            int rw = e / DMAX, m = e % DMAX;
            int dg = __ldcg(&g_deg[bid * RPB + rw]);
            dg = (dg > DMAX) ? DMAX : dg;
            snbroff[e] = (m < dg) ? __ldcg(&g_nbr[(bid * RPB + rw) * N + m]) * N
                                  : NN;            // points at the zero row
            if (m == 0) sdegp[rw] = (dg + 3) & ~3;
        }
    }
    __syncthreads();
    // Cache this thread's 24 B' column values in registers for all 50 iters.
    float Breg[24];
    #pragma unroll
    for (int j = 0; j < 24; j++) Breg[j] = dyn[(24 * c + j) * N + q];
    CSYNC();

    // ============ 50 MPM iterations, one cluster.sync each ==================
    // F positively homogeneous: exact norm carried as scalar; partials
    // published in the same release (CSYNC) as the M rows.
    const int gbase = bid * RPB * N;
    for (int it = 0; it < ITERS; it++) {
        const float* __restrict__ Min  = g_M[it & 1];
        float*       __restrict__ Mout = g_M[(it + 1) & 1];

        // scale computed redundantly per warp: no block sync needed for it
        float scale;
        if (it == 0) scale = 1.f;
        else {
            float p = (lane < CSZ) ? __ldcg(&g_part[(it - 1) & 1][lane]) : 0.f;
            p += __shfl_xor_sync(~0u, p, 8);
            p += __shfl_xor_sync(~0u, p, 4);
            p += __shfl_xor_sync(~0u, p, 2);
            p += __shfl_xor_sync(~0u, p, 1);
            scale = rsqrtf(__shfl_sync(~0u, p, 0));
        }

        // X update: raw = x*nd + sum of neighbor M rows (batched LDGs)
        float a[(RPB * N + NT - 1) / NT];
        {
            int ne = 0;
            for (int e = t; e < RPB * N; e += NT, ne++) {
                int rw = e / 96;
                float raw = sX[e] * sND[e];
                int dp = sdegp[rw];
                const int* off = &snbroff[rw * DMAX];
                for (int m = 0; m < dp; m += 4) {
                    int o0 = off[m], o1 = off[m + 1], o2 = off[m + 2], o3 = off[m + 3];
                    raw += __ldcg(&Min[o0 + kk]) + __ldcg(&Min[o1 + kk])
                         + __ldcg(&Min[o2 + kk]) + __ldcg(&Min[o3 + kk]);
                }
                a[ne] = raw;
            }
        }
        float sq = 0.f;
        {
            int ne = 0;
            for (int e = t; e < RPB * N; e += NT, ne++) {
                float v = a[ne] * scale;
                sX[e] = v;
                sq += v * v;
            }
        }
        #pragma unroll
        for (int o = 16; o; o >>= 1) sq += __shfl_xor_sync(~0u, sq, o);
        if (lane == 0) red[wid] = sq;
        __syncthreads();                 // publishes new sX + red
        if (t == 0) {
            float s2 = 0.f;
            #pragma unroll
            for (int w = 0; w < 12; w++) s2 += red[w];
            __stcg(&g_part[it & 1][bid], s2);
        }

        if (it != ITERS - 1) {
            // M[row,k] = max_{l!=k} B'[l,k] * x_row[l]
            // thread (k=q, quarter c): 24 l's from registers, float4 x loads.
            #pragma unroll
            for (int r2 = 0; r2 < RPB; r2++) {
                const float4* xp = (const float4*)&sX[r2 * N + 24 * c];
                float ma = 0.f, mb = 0.f;
                #pragma unroll
                for (int j = 0; j < 6; j++) {
                    float4 xv = xp[j];
                    ma = fmaxf(ma, Breg[4 * j + 0] * xv.x);
                    mb = fmaxf(mb, Breg[4 * j + 1] * xv.y);
                    ma = fmaxf(ma, Breg[4 * j + 2] * xv.z);
                    mb = fmaxf(mb, Breg[4 * j + 3] * xv.w);
                }
                float m = fmaxf(ma, mb);
                m = fmaxf(m, __shfl_down_sync(~0u, m, 1));
                m = fmaxf(m, __shfl_down_sync(~0u, m, 2));
                if (c == 0) __stcg(&Mout[gbase + r2 * N + q], m);
            }
        }
        CSYNC();
    }

    // ============ final normalize + write ===================================
    {
        float p = (lane < CSZ) ? __ldcg(&g_part[(ITERS - 1) & 1][lane]) : 0.f;
        p += __shfl_xor_sync(~0u, p, 8);
        p += __shfl_xor_sync(~0u, p, 4);
        p += __shfl_xor_sync(~0u, p, 2);
        p += __shfl_xor_sync(~0u, p, 1);
        float os = rsqrtf(__shfl_sync(~0u, p, 0));
        for (int e = t; e < RPB * N; e += NT)
            out[gbase + e] = sX[e] * os;
    }
}

// ---------------- launch ----------------
extern "C" void kernel_launch(void* const* d_in, const int* in_sizes, int n_in,
                              void* d_out, int out_size) {
    const float* x   = (const float*)d_in[0];
    const int*   ei  = (const int*)  d_in[1];
    const float* adj = (const float*)d_in[2];
    const float* W1  = (const float*)d_in[3];
    // d_in[4] = b1 (cancelled by BN)
    const float* g1  = (const float*)d_in[5];
    const float* be1 = (const float*)d_in[6];
    const float* W2  = (const float*)d_in[7];
    // d_in[8] = b2 (cancelled by BN)
    const float* g2  = (const float*)d_in[9];
    const float* be2 = (const float*)d_in[10];
    const float* Wmu = (const float*)d_in[11];
    const float* bmu = (const float*)d_in[12];
    const float* Wlv = (const float*)d_in[13];
    const float* blv = (const float*)d_in[14];
    const float* Wd1 = (const float*)d_in[15];
    const float* bd1 = (const float*)d_in[16];
    const float* Wd2 = (const float*)d_in[17];
    const float* bd2 = (const float*)d_in[18];
    const float* eps = (const float*)d_in[19];
    float* o = (float*)d_out;

    // Probe 16-CTA non-portable cluster support (deterministic host query).
    cudaFuncSetAttribute(fused_graphvae<16>,
                         cudaFuncAttributeNonPortableClusterSizeAllowed, 1);
    cudaLaunchAttribute at16[1];
    at16[0].id = cudaLaunchAttributeClusterDimension;
    at16[0].val.clusterDim = {16, 1, 1};
    cudaLaunchConfig_t cfg16 = {};
    cfg16.gridDim = dim3(16, 1, 1);
    cfg16.blockDim = dim3(NT, 1, 1);
    cfg16.dynamicSmemBytes = 0;
    cfg16.attrs = at16;
    cfg16.numAttrs = 1;
    int nclus = 0;
    cudaError_t qe = cudaOccupancyMaxActiveClusters(&nclus, fused_graphvae<16>, &cfg16);
    if (qe != cudaSuccess) { (void)cudaGetLastError(); nclus = 0; }  // clear

    if (nclus >= 1) {
        cudaLaunchKernelEx(&cfg16, fused_graphvae<16>,
            x, ei, adj, W1, g1, be1, W2, g2, be2,
            Wmu, bmu, Wlv, blv, Wd1, bd1, Wd2, bd2, eps, o);
    } else {
        cudaLaunchAttribute at8[1];
        at8[0].id = cudaLaunchAttributeClusterDimension;
        at8[0].val.clusterDim = {8, 1, 1};
        cudaLaunchConfig_t cfg8 = {};
        cfg8.gridDim = dim3(8, 1, 1);
        cfg8.blockDim = dim3(NT, 1, 1);
        cfg8.dynamicSmemBytes = 0;
        cfg8.attrs = at8;
        cfg8.numAttrs = 1;
        cudaLaunchKernelEx(&cfg8, fused_graphvae<8>,
            x, ei, adj, W1, g1, be1, W2, g2, be2,
            Wmu, bmu, Wlv, blv, Wd1, bd1, Wd2, bd2, eps, o);
    }
}

// round 11
// speedup vs baseline: 1.5112x; 1.0395x over previous
#include <cuda_runtime.h>
#include <math.h>

#define N        96
#define NT       384     // prologue threads per CTA
#define NT2      768     // MPM threads per CTA (24 warps)
#define NN       9216
#define IN_DIM   64
#define HID      256
#define ZD       64
#define E        1024
#define NUM_LOGITS 4656
#define ITERS    50
#define UTRI     4560
#define DMAX     32      // padded neighbor-list capacity

// ---------------- device scratch (no allocations allowed) ----------------
__device__ float g_Anorm[NN];
__device__ float g_T[N * HID];
__device__ float g_P[N * HID];
__device__ float g_H[N * HID];
__device__ float g_gv[HID];
__device__ float g_B[NN];
__device__ float g_ND[NN];            // node_sim matrix (prologue -> MPM)
__device__ float g_degA[N];
__device__ int   g_deg[N];
__device__ int   g_nbr[NN];
__device__ float g_M[2][NN + N];      // +1 zero row for padded neighbors
__device__ float g_part[16];          // per-CTA sum-of-squares partials

// Cluster-wide barrier, release/acquire across the cluster.
#define CSYNC() do { \
    asm volatile("barrier.cluster.arrive.aligned;" ::: "memory"); \
    asm volatile("barrier.cluster.wait.aligned;"   ::: "memory"); \
} while (0)

// =========================== PROLOGUE KERNEL ===============================
template <int CSZ>
__global__ void __launch_bounds__(NT, 1)
prologue_k(
    const float* __restrict__ x,   const int* __restrict__ ei,
    const float* __restrict__ adj,
    const float* __restrict__ W1,  const float* __restrict__ g1,  const float* __restrict__ be1,
    const float* __restrict__ W2,  const float* __restrict__ g2,  const float* __restrict__ be2,
    const float* __restrict__ Wmu, const float* __restrict__ bmu,
    const float* __restrict__ Wlv, const float* __restrict__ blv,
    const float* __restrict__ Wd1, const float* __restrict__ bd1,
    const float* __restrict__ Wd2, const float* __restrict__ bd2,
    const float* __restrict__ eps)
{
    constexpr int RPB = N / CSZ;
    constexpr int CPC = HID / CSZ;

    __shared__ float dyn[NN];
    __shared__ float sdb[N];
    __shared__ float stmp[N];

    const int t    = threadIdx.x;
    const int bid  = blockIdx.x;
    const int lane = t & 31, wid = t >> 5;
    const int kk   = t % 96;

    // ---- Ph1: adjacency (CTA 0) + gemm1 (others) ----
    if (bid == 0) {
        for (int i = t; i < NN; i += NT) dyn[i] = 0.f;
        __syncthreads();
        for (int e = t; e < E; e += NT)
            dyn[ei[e] * N + ei[E + e]] = 1.f;      // identical-value races OK
        __syncthreads();
        if (t < N) dyn[t * (N + 1)] = 1.f;         // A = max(A, I)
        __syncthreads();
        for (int rr = wid; rr < N; rr += 12) {
            float s = dyn[rr * N + lane] + dyn[rr * N + lane + 32]
                    + dyn[rr * N + lane + 64];
            #pragma unroll
            for (int o = 16; o; o >>= 1) s += __shfl_xor_sync(~0u, s, o);
            if (lane == 0) stmp[rr] = rsqrtf(s);
        }
        __syncthreads();
        for (int i = t; i < NN; i += NT) {
            int rr = i / N, cc = i - rr * N;
            __stcg(&g_Anorm[i], dyn[i] * stmp[rr] * stmp[cc]);
        }
        if (t < N) {
            float s = 0.f; int cnt = 0;
            for (int j = 0; j < N; j++) {
                float v = adj[t * N + j];
                s += v;
                if (v > 0.5f) __stcg(&g_nbr[t * N + cnt++], j);
            }
            __stcg(&g_degA[t], s + 1.f);           // Agt diag forced to 1
            __stcg(&g_deg[t], cnt);
        }
    } else {
        // T = x @ W1 (bias b1 exactly cancelled by BN)
        for (int e = t; e < N * IN_DIM; e += NT) dyn[e] = x[e];
        __syncthreads();
        for (int qq = (bid - 1) * NT + t; qq < N * (HID / 4); qq += (CSZ - 1) * NT) {
            int i = qq >> 6, c4 = (qq & 63) << 2;
            float a0 = 0, a1 = 0, a2 = 0, a3 = 0;
            #pragma unroll
            for (int k2 = 0; k2 < IN_DIM; k2++) {
                float xv = dyn[i * IN_DIM + k2];
                float4 w = *(const float4*)&W1[k2 * HID + c4];
                a0 += xv * w.x; a1 += xv * w.y; a2 += xv * w.z; a3 += xv * w.w;
            }
            __stcg((float4*)&g_T[i * HID + c4], make_float4(a0, a1, a2, a3));
        }
    }
    CSYNC();

    auto gcn = [&]() {
        for (int e = t; e < RPB * N; e += NT)
            dyn[e] = __ldcg(&g_Anorm[bid * RPB * N + e]);
        __syncthreads();
        for (int qq = t; qq < RPB * (HID / 4); qq += NT) {
            int rr = qq >> 6, c4 = (qq & 63) << 2;
            float a0 = 0, a1 = 0, a2 = 0, a3 = 0;
            #pragma unroll 4
            for (int j = 0; j < N; j++) {
                float av = dyn[rr * N + j];
                float4 tv = __ldcg((const float4*)&g_T[j * HID + c4]);
                a0 += av * tv.x; a1 += av * tv.y; a2 += av * tv.z; a3 += av * tv.w;
            }
            __stcg((float4*)&g_P[(bid * RPB + rr) * HID + c4],
                   make_float4(a0, a1, a2, a3));
        }
    };
    auto bn = [&](const float* gamma, const float* beta, int write_h, int do_gv) {
        for (int cc = wid; cc < CPC; cc += 12) {
            int col = bid * CPC + cc;
            float v0 = __ldcg(&g_P[lane * HID + col]);
            float v1 = __ldcg(&g_P[(lane + 32) * HID + col]);
            float v2 = __ldcg(&g_P[(lane + 64) * HID + col]);
            float s = v0 + v1 + v2;
            float qd = v0 * v0 + v1 * v1 + v2 * v2;
            #pragma unroll
            for (int o = 16; o; o >>= 1) {
                s  += __shfl_xor_sync(~0u, s, o);
                qd += __shfl_xor_sync(~0u, qd, o);
            }
            float m   = s * (1.f / N);
            float var = qd * (1.f / N) - m * m;
            float inv = rsqrtf(var + 1e-5f) * gamma[col];
            float bb  = beta[col];
            float h0 = fmaxf((v0 - m) * inv + bb, 0.f);
            float h1 = fmaxf((v1 - m) * inv + bb, 0.f);
            float h2 = fmaxf((v2 - m) * inv + bb, 0.f);
            if (write_h) {
                __stcg(&g_H[lane * HID + col], h0);
                __stcg(&g_H[(lane + 32) * HID + col], h1);
                __stcg(&g_H[(lane + 64) * HID + col], h2);
            }
            if (do_gv) {
                float gs = h0 + h1 + h2;
                #pragma unroll
                for (int o = 16; o; o >>= 1) gs += __shfl_xor_sync(~0u, gs, o);
                if (lane == 0) __stcg(&g_gv[col], gs * (1.f / N));
            }
        }
    };

    gcn();             CSYNC();
    bn(g1, be1, 1, 0); CSYNC();

    // gemm2: T = H @ W2
    {
        for (int e = t; e < RPB * HID; e += NT)
            dyn[e] = __ldcg(&g_H[bid * RPB * HID + e]);
        __syncthreads();
        for (int qq = t; qq < RPB * (HID / 4); qq += NT) {
            int rr = qq >> 6, c4 = (qq & 63) << 2;
            float a0 = 0, a1 = 0, a2 = 0, a3 = 0;
            #pragma unroll 4
            for (int k2 = 0; k2 < HID; k2++) {
                float hv = dyn[rr * HID + k2];
                float4 w = *(const float4*)&W2[k2 * HID + c4];
                a0 += hv * w.x; a1 += hv * w.y; a2 += hv * w.z; a3 += hv * w.w;
            }
            __stcg((float4*)&g_T[(bid * RPB + rr) * HID + c4],
                   make_float4(a0, a1, a2, a3));
        }
    }
    CSYNC();
    gcn();             CSYNC();
    bn(g2, be2, 0, 1); CSYNC();

    // head (replicated per CTA) + decoder -> symmetric B (diag = 1)
    {
        if (t < HID) dyn[t] = __ldcg(&g_gv[t]);
        __syncthreads();
        if (t < ZD) {
            float mu = bmu[t], lv = blv[t];
            #pragma unroll 4
            for (int k2 = 0; k2 < HID; k2++) {
                float g = dyn[k2];
                mu += g * Wmu[k2 * ZD + t];
                lv += g * Wlv[k2 * ZD + t];
            }
            lv = fminf(fmaxf(lv, -4.f), 4.f);
            dyn[HID + t] = mu + eps[t] * expf(0.5f * lv);
        }
        __syncthreads();
        if (t < HID) {
            float a = bd1[t];
            #pragma unroll
            for (int d = 0; d < ZD; d++) a += dyn[HID + d] * Wd1[d * HID + t];
            dyn[HID + ZD + t] = fmaxf(a, 0.f);     // d1
        }
        __syncthreads();
        for (int u = bid * NT + t; u < UTRI; u += CSZ * NT) {
            int uu = u, rr = 0, rem = N - 1;
            while (uu >= rem) { uu -= rem; rem--; rr++; }
            int cc = rr + 1 + uu;
            float a = bd2[u];
            #pragma unroll 4
            for (int k2 = 0; k2 < HID; k2++)
                a += dyn[HID + ZD + k2] * Wd2[k2 * NUM_LOGITS + u];
            float th  = tanhf(a);
            float sig = 1.f / (1.f + expf(-th));
            __stcg(&g_B[rr * N + cc], sig);
            __stcg(&g_B[cc * N + rr], sig);
        }
        if (bid == 0 && t < N) __stcg(&g_B[t * (N + 1)], 1.f);
    }
    CSYNC();

    // prep: nd matrix, M0, zero row
    {
        for (int i = t; i < NN; i += NT) {
            int rr = i / N, cc = i - rr * N;
            dyn[i] = (rr == cc) ? 0.f : __ldcg(&g_B[i]);
        }
        __syncthreads();
        if (t < N) {                  // column stats (B symmetric): conflict-free
            float db = 1.f, mx = 0.f;
            #pragma unroll 4
            for (int l = 0; l < N; l++) {
                float b = dyn[l * N + t];
                db += b;
                mx = fmaxf(mx, b);
            }
            sdb[t] = db;
            float m0 = mx * (1.f / N);            // X0 uniform
            for (int r2 = 0; r2 < RPB; r2++)
                __stcg(&g_M[0][(bid * RPB + r2) * N + t], m0);
            if (bid == 0) { __stcg(&g_M[0][NN + t], 0.f); __stcg(&g_M[1][NN + t], 0.f); }
        }
        __syncthreads();
        for (int e = t; e < RPB * N; e += NT) {
            int rw = e / 96;
            __stcg(&g_ND[bid * RPB * N + e],
                   1.f / (fabsf(__ldcg(&g_degA[bid * RPB + rw]) - sdb[e % 96]) + 1.f));
        }
    }
}

// ============================= MPM KERNEL ==================================
// X_t = F^t(X0)/||F^t(X0)||  (F positively homogeneous) -> intermediate
// normalizations are redundant; apply an exact uniform rescale every 4 iters
// purely for fp32 range (growth <= ~25x/iter), and normalize once at the end.
template <int CSZ>
__global__ void __launch_bounds__(NT2, 1)
mpm_k(float* __restrict__ out)
{
    constexpr int RPB = N / CSZ;          // 6 (or 12)
    constexpr int XE  = RPB * N;          // 576 (or 1152)

    __shared__ __align__(16) float sX[XE];
    __shared__ float sND[XE];
    __shared__ int   snbroff[RPB * DMAX];
    __shared__ int   sdegp[RPB];
    __shared__ float red[24];

    const int t    = threadIdx.x;         // 0..767
    const int bid  = blockIdx.x;
    const int lane = t & 31, wid = t >> 5;
    const int q    = t >> 3;              // M-compute column 0..95
    const int c    = t & 7;               // M-compute l-octant 0..7
    const int gbase = bid * XE;

    for (int e = t; e < XE; e += NT2) {
        sX[e]  = 1.f / N;                  // X0 uniform
        sND[e] = __ldcg(&g_ND[gbase + e]);
    }
    for (int e = t; e < RPB * DMAX; e += NT2) {
        int rw = e / DMAX, m = e % DMAX;
        int dg = __ldcg(&g_deg[bid * RPB + rw]);
        dg = (dg > DMAX) ? DMAX : dg;
        snbroff[e] = (m < dg) ? __ldcg(&g_nbr[(bid * RPB + rw) * N + m]) * N
                              : NN;        // padded -> zero row
        if (m == 0) sdegp[rw] = (dg + 3) & ~3;
    }
    // B' column q, octant c, cached in registers for all 50 iterations
    float Breg[12];
    #pragma unroll
    for (int j = 0; j < 12; j++) {
        int l = 12 * c + j;
        Breg[j] = (l == q) ? 0.f : __ldcg(&g_B[l * N + q]);
    }
    __syncthreads();

    for (int it = 0; it < ITERS; it++) {
        const float* __restrict__ Min  = g_M[it & 1];
        float*       __restrict__ Mout = g_M[(it + 1) & 1];

        float scale = 1.f;
        if (it > 0 && (it & 3) == 0) {      // uniform rescale (range control)
            float p = (lane < CSZ) ? __ldcg(&g_part[lane]) : 0.f;
            p += __shfl_xor_sync(~0u, p, 8);
            p += __shfl_xor_sync(~0u, p, 4);
            p += __shfl_xor_sync(~0u, p, 2);
            p += __shfl_xor_sync(~0u, p, 1);
            scale = rsqrtf(__shfl_sync(~0u, p, 0));
        }
        const bool pub = ((it & 3) == 3) || (it == ITERS - 1);

        float sq = 0.f;
        for (int e = t; e < XE; e += NT2) {
            int rw = e / 96, col = e % 96;
            float raw = sX[e] * sND[e];
            int dp = sdegp[rw];
            const int* off = &snbroff[rw * DMAX];
            for (int m = 0; m < dp; m += 4) {
                raw += __ldcg(&Min[off[m] + col])     + __ldcg(&Min[off[m + 1] + col])
                     + __ldcg(&Min[off[m + 2] + col]) + __ldcg(&Min[off[m + 3] + col]);
            }
            float v = raw * scale;
            sX[e] = v;
            if (pub) sq += v * v;
        }
        if (pub) {
            #pragma unroll
            for (int o = 16; o; o >>= 1) sq += __shfl_xor_sync(~0u, sq, o);
            if (lane == 0) red[wid] = sq;
        }
        __syncthreads();                    // publishes sX (and red)
        if (pub && t == 0) {
            float s2 = 0.f;
            #pragma unroll
            for (int w = 0; w < 24; w++) s2 += red[w];
            __stcg(&g_part[bid], s2);
        }

        if (it != ITERS - 1) {
            // M[row,q] = max_{l != q} B[q,l] * x_row[l]; B symmetric.
            #pragma unroll
            for (int r2 = 0; r2 < RPB; r2++) {
                const float4* xp = (const float4*)&sX[r2 * N + 12 * c];
                float4 x0 = xp[0], x1 = xp[1], x2 = xp[2];
                float ma, mb;
                ma =           Breg[0]  * x0.x;  mb =           Breg[1]  * x0.y;
                ma = fmaxf(ma, Breg[2]  * x0.z); mb = fmaxf(mb, Breg[3]  * x0.w);
                ma = fmaxf(ma, Breg[4]  * x1.x); mb = fmaxf(mb, Breg[5]  * x1.y);
                ma = fmaxf(ma, Breg[6]  * x1.z); mb = fmaxf(mb, Breg[7]  * x1.w);
                ma = fmaxf(ma, Breg[8]  * x2.x); mb = fmaxf(mb, Breg[9]  * x2.y);
                ma = fmaxf(ma, Breg[10] * x2.z); mb = fmaxf(mb, Breg[11] * x2.w);
                float m = fmaxf(ma, mb);
                m = fmaxf(m, __shfl_down_sync(~0u, m, 4));
                m = fmaxf(m, __shfl_down_sync(~0u, m, 2));
                m = fmaxf(m, __shfl_down_sync(~0u, m, 1));
                if (c == 0) __stcg(&Mout[gbase + r2 * N + q], m);
            }
        }
        CSYNC();
    }

    // final normalization (the only one that matters mathematically)
    {
        float p = (lane < CSZ) ? __ldcg(&g_part[lane]) : 0.f;
        p += __shfl_xor_sync(~0u, p, 8);
        p += __shfl_xor_sync(~0u, p, 4);
        p += __shfl_xor_sync(~0u, p, 2);
        p += __shfl_xor_sync(~0u, p, 1);
        float os = rsqrtf(__shfl_sync(~0u, p, 0));
        for (int e = t; e < XE; e += NT2)
            out[gbase + e] = sX[e] * os;
    }
}

// ---------------- launch ----------------
extern "C" void kernel_launch(void* const* d_in, const int* in_sizes, int n_in,
                              void* d_out, int out_size) {
    const float* x   = (const float*)d_in[0];
    const int*   ei  = (const int*)  d_in[1];
    const float* adj = (const float*)d_in[2];
    const float* W1  = (const float*)d_in[3];
    // d_in[4] = b1 (cancelled by BN)
    const float* g1  = (const float*)d_in[5];
    const float* be1 = (const float*)d_in[6];
    const float* W2  = (const float*)d_in[7];
    // d_in[8] = b2 (cancelled by BN)
    const float* g2  = (const float*)d_in[9];
    const float* be2 = (const float*)d_in[10];
    const float* Wmu = (const float*)d_in[11];
    const float* bmu = (const float*)d_in[12];
    const float* Wlv = (const float*)d_in[13];
    const float* blv = (const float*)d_in[14];
    const float* Wd1 = (const float*)d_in[15];
    const float* bd1 = (const float*)d_in[16];
    const float* Wd2 = (const float*)d_in[17];
    const float* bd2 = (const float*)d_in[18];
    const float* eps = (const float*)d_in[19];
    float* o = (float*)d_out;

    // Probe 16-CTA non-portable cluster support (deterministic host queries).
    cudaFuncSetAttribute(prologue_k<16>,
                         cudaFuncAttributeNonPortableClusterSizeAllowed, 1);
    cudaFuncSetAttribute(mpm_k<16>,
                         cudaFuncAttributeNonPortableClusterSizeAllowed, 1);

    cudaLaunchAttribute at16[1];
    at16[0].id = cudaLaunchAttributeClusterDimension;
    at16[0].val.clusterDim = {16, 1, 1};

    cudaLaunchConfig_t cfgP16 = {};
    cfgP16.gridDim = dim3(16, 1, 1);
    cfgP16.blockDim = dim3(NT, 1, 1);
    cfgP16.attrs = at16;  cfgP16.numAttrs = 1;

    cudaLaunchConfig_t cfgM16 = {};
    cfgM16.gridDim = dim3(16, 1, 1);
    cfgM16.blockDim = dim3(NT2, 1, 1);
    cfgM16.attrs = at16;  cfgM16.numAttrs = 1;

    int np = 0, nm = 0;
    cudaError_t e1 = cudaOccupancyMaxActiveClusters(&np, prologue_k<16>, &cfgP16);
    cudaError_t e2 = cudaOccupancyMaxActiveClusters(&nm, mpm_k<16>, &cfgM16);
    if (e1 != cudaSuccess || e2 != cudaSuccess) { (void)cudaGetLastError(); np = nm = 0; }

    if (np >= 1 && nm >= 1) {
        cudaLaunchKernelEx(&cfgP16, prologue_k<16>,
            x, ei, adj, W1, g1, be1, W2, g2, be2,
            Wmu, bmu, Wlv, blv, Wd1, bd1, Wd2, bd2, eps);
        cudaLaunchKernelEx(&cfgM16, mpm_k<16>, o);
    } else {
        cudaLaunchAttribute at8[1];
        at8[0].id = cudaLaunchAttributeClusterDimension;
        at8[0].val.clusterDim = {8, 1, 1};
        cudaLaunchConfig_t cfgP8 = {};
        cfgP8.gridDim = dim3(8, 1, 1);
        cfgP8.blockDim = dim3(NT, 1, 1);
        cfgP8.attrs = at8;  cfgP8.numAttrs = 1;
        cudaLaunchConfig_t cfgM8 = {};
        cfgM8.gridDim = dim3(8, 1, 1);
        cfgM8.blockDim = dim3(NT2, 1, 1);
        cfgM8.attrs = at8;  cfgM8.numAttrs = 1;
        cudaLaunchKernelEx(&cfgP8, prologue_k<8>,
            x, ei, adj, W1, g1, be1, W2, g2, be2,
            Wmu, bmu, Wlv, blv, Wd1, bd1, Wd2, bd2, eps);
        cudaLaunchKernelEx(&cfgM8, mpm_k<8>, o);
    }
}

// round 13
// speedup vs baseline: 1.6716x; 1.1062x over previous
#include <cuda_runtime.h>
#include <math.h>

#define N        96
#define NT       384     // prologue threads per CTA
#define NT2      768     // MPM threads per CTA (24 warps)
#define NN       9216
#define ATS      97      // padded stride for transposed A_norm in smem
#define IN_DIM   64
#define HID      256
#define ZD       64
#define E        1024
#define NUM_LOGITS 4656
#define ITERS    50
#define UTRI     4560
#define DMAX     32      // padded neighbor-list capacity

// ---------------- device scratch (no allocations allowed) ----------------
__device__ float g_Anorm[NN];
__device__ float g_Ht[N * HID];       // layer-1 activations, TRANSPOSED: Ht[k*96+r]
__device__ float g_gv[HID];
__device__ float g_B[NN];
__device__ float g_ND[NN];
__device__ float g_degA[N];
__device__ int   g_deg[N];
__device__ int   g_nbr[NN];
__device__ float g_M[2][NN + N];      // +1 zero row for padded neighbors
__device__ float g_part[16];          // per-CTA sum-of-squares partials

#define C_ARRIVE() asm volatile("barrier.cluster.arrive.aligned;" ::: "memory")
#define C_WAIT()   asm volatile("barrier.cluster.wait.aligned;"   ::: "memory")
#define CSYNC() do { C_ARRIVE(); C_WAIT(); } while (0)

// =========================== PROLOGUE KERNEL ===============================
// Column-distributed: CTA b owns output columns [b*CPC, (b+1)*CPC) of each
// layer for ALL 96 rows -> GCN-matmul + BN + ReLU fuse with no cross-CTA sync
// inside a layer.
// NOTE: A_norm is NOT symmetric (edge_index is directed!) -> it is staged
// TRANSPOSED in smem (At[j*97+r] = A_norm[r][j]) so the gcn inner loop reads
// true rows conflict-free. adj_gt and B, by contrast, ARE symmetric.
template <int CSZ>
__global__ void __launch_bounds__(NT, 1)
prologue_k(
    const float* __restrict__ x,   const int* __restrict__ ei,
    const float* __restrict__ adj,
    const float* __restrict__ W1,  const float* __restrict__ g1,  const float* __restrict__ be1,
    const float* __restrict__ W2,  const float* __restrict__ g2,  const float* __restrict__ be2,
    const float* __restrict__ Wmu, const float* __restrict__ bmu,
    const float* __restrict__ Wlv, const float* __restrict__ blv,
    const float* __restrict__ Wd1, const float* __restrict__ bd1,
    const float* __restrict__ Wd2, const float* __restrict__ bd2,
    const float* __restrict__ eps)
{
    constexpr int CPC = HID / CSZ;     // columns per CTA (16 / 32)
    constexpr int CW  = CPC / 4;       // columns per thread (4 / 8)
    constexpr int STP = CPC + 1;       // padded smem stride
    constexpr int RPB = N / CSZ;

    extern __shared__ float sm[];
    float* dyn = sm;                   // 96*ATS floats (adj linear / x / A_norm^T)
    float* sT  = sm + N * ATS;         // 96*STP (T1cols, then T2cols)
    float* sP  = sT + 96 * STP;        // 96*STP (pre-BN columns)

    __shared__ float stmp[N];
    __shared__ float sred[8][N];

    const int t    = threadIdx.x;
    const int bid  = blockIdx.x;
    const int lane = t & 31, wid = t >> 5;
    const int r    = t % 96, g = t / 96;         // row, column-group
    const int lc   = g * CW;                     // local col base
    const int gcol = bid * CPC + lc;             // global col base

    // ---------------- P1: adjacency (CTA0) + gemm1 (all CTAs) -------------
    if (bid == 0) {
        for (int i = t; i < NN; i += NT) dyn[i] = 0.f;     // linear layout here
        __syncthreads();
        for (int e = t; e < E; e += NT)
            dyn[ei[e] * N + ei[E + e]] = 1.f;     // identical-value races OK
        __syncthreads();
        if (t < N) dyn[t * (N + 1)] = 1.f;        // A = max(A, I)
        __syncthreads();
        for (int rr = wid; rr < N; rr += 12) {    // ROW sums (directed A!)
            float s = dyn[rr * N + lane] + dyn[rr * N + lane + 32]
                    + dyn[rr * N + lane + 64];
            #pragma unroll
            for (int o = 16; o; o >>= 1) s += __shfl_xor_sync(~0u, s, o);
            if (lane == 0) stmp[rr] = rsqrtf(s);
        }
        __syncthreads();
        for (int i = t; i < NN; i += NT) {
            int rr = i / N, cc = i - rr * N;
            g_Anorm[i] = dyn[i] * stmp[rr] * stmp[cc];
        }
        if (t < N) {                 // adj_gt IS symmetric -> coalesced col read
            float s = 0.f; int cnt = 0;
            #pragma unroll 4
            for (int j = 0; j < N; j++) {
                float v = adj[j * N + t];
                s += v;
                if (v > 0.5f) g_nbr[t * N + cnt++] = j;
            }
            g_degA[t] = s + 1.f;                  // Agt diag forced to 1
            g_deg[t]  = cnt;
        }
        __syncthreads();                          // dyn free for x-stage
    }
    // stage x transposed+padded: dyn[k*ATS + r] (coalesced LDG, clean STS)
    for (int i = t; i < N * IN_DIM; i += NT) {
        int rr = i >> 6, k = i & 63;
        dyn[k * ATS + rr] = x[i];
    }
    __syncthreads();
    {   // T1cols = x @ W1 (bias b1 exactly cancelled by BN)
        float acc[CW];
        #pragma unroll
        for (int c = 0; c < CW; c++) acc[c] = 0.f;
        #pragma unroll 8
        for (int k = 0; k < IN_DIM; k++) {
            float xv = dyn[k * ATS + r];
            #pragma unroll
            for (int c4 = 0; c4 < CW / 4; c4++) {
                float4 w = *(const float4*)&W1[k * HID + gcol + 4 * c4];
                acc[4*c4+0] += xv * w.x; acc[4*c4+1] += xv * w.y;
                acc[4*c4+2] += xv * w.z; acc[4*c4+3] += xv * w.w;
            }
        }
        #pragma unroll
        for (int c = 0; c < CW; c++) sT[r * STP + lc + c] = acc[c];
    }
    CSYNC();

    // ---- load A_norm TRANSPOSED into smem (kept for both layers) ----------
    // At[cc*ATS + rr] = A_norm[rr][cc]; gcn thread r reads At[j*ATS + r]
    // = A_norm[r][j] (true row), lanes consecutive in r -> conflict-free.
    for (int i = t; i < NN; i += NT) {
        int rr = i / N, cc = i - rr * N;
        dyn[cc * ATS + rr] = g_Anorm[i];
    }
    __syncthreads();

    // gcn + BN + relu for this CTA's columns; sT -> sP -> (H / gv)
    auto gcnbn = [&](const float* gamma, const float* beta, bool writeH, bool dogv) {
        float acc[CW];
        #pragma unroll
        for (int c = 0; c < CW; c++) acc[c] = 0.f;
        #pragma unroll 4
        for (int j = 0; j < N; j++) {
            float a = dyn[j * ATS + r];           // A_norm[r][j]  (correct row)
            #pragma unroll
            for (int c = 0; c < CW; c++)
                acc[c] += a * sT[j * STP + lc + c];
        }
        #pragma unroll
        for (int c = 0; c < CW; c++) sP[r * STP + lc + c] = acc[c];
        __syncthreads();
        for (int cc = wid; cc < CPC; cc += 12) {  // warp-per-column BN
            int col = bid * CPC + cc;
            float v0 = sP[lane * STP + cc];
            float v1 = sP[(lane + 32) * STP + cc];
            float v2 = sP[(lane + 64) * STP + cc];
            float s = v0 + v1 + v2, qd = v0*v0 + v1*v1 + v2*v2;
            #pragma unroll
            for (int o = 16; o; o >>= 1) {
                s  += __shfl_xor_sync(~0u, s, o);
                qd += __shfl_xor_sync(~0u, qd, o);
            }
            float m   = s * (1.f / N);
            float var = qd * (1.f / N) - m * m;
            float inv = rsqrtf(var + 1e-5f) * gamma[col];
            float bb  = beta[col];
            float h0 = fmaxf((v0 - m) * inv + bb, 0.f);
            float h1 = fmaxf((v1 - m) * inv + bb, 0.f);
            float h2 = fmaxf((v2 - m) * inv + bb, 0.f);
            if (writeH) {                          // transposed -> coalesced
                g_Ht[col * 96 + lane]      = h0;
                g_Ht[col * 96 + lane + 32] = h1;
                g_Ht[col * 96 + lane + 64] = h2;
            }
            if (dogv) {
                float gs = h0 + h1 + h2;
                #pragma unroll
                for (int o = 16; o; o >>= 1) gs += __shfl_xor_sync(~0u, gs, o);
                if (lane == 0) g_gv[col] = gs * (1.f / N);
            }
        }
    };

    gcnbn(g1, be1, true, false);     // layer 1 -> g_Ht
    CSYNC();

    // ---------------- layer 2: gemm2 + gcn + BN (one phase) ---------------
    {
        float acc[CW];
        #pragma unroll
        for (int c = 0; c < CW; c++) acc[c] = 0.f;
        #pragma unroll 4
        for (int k = 0; k < HID; k++) {
            float hv = g_Ht[k * 96 + r];          // transposed -> coalesced
            #pragma unroll
            for (int c4 = 0; c4 < CW / 4; c4++) {
                float4 w = *(const float4*)&W2[k * HID + gcol + 4 * c4];
                acc[4*c4+0] += hv * w.x; acc[4*c4+1] += hv * w.y;
                acc[4*c4+2] += hv * w.z; acc[4*c4+3] += hv * w.w;
            }
        }
        __syncthreads();
        #pragma unroll
        for (int c = 0; c < CW; c++) sT[r * STP + lc + c] = acc[c];
    }
    __syncthreads();
    gcnbn(g2, be2, false, true);     // layer 2 -> g_gv only
    CSYNC();

    // ---------------- head (replicated) + decoder -> B ---------------------
    {
        if (t < HID) dyn[t] = g_gv[t];            // dyn free (A_norm done)
        __syncthreads();
        if (t < ZD) {
            float mu = bmu[t], lv = blv[t];
            #pragma unroll 8
            for (int k2 = 0; k2 < HID; k2++) {
                float gg = dyn[k2];
                mu += gg * Wmu[k2 * ZD + t];
                lv += gg * Wlv[k2 * ZD + t];
            }
            lv = fminf(fmaxf(lv, -4.f), 4.f);
            dyn[HID + t] = mu + eps[t] * expf(0.5f * lv);
        }
        __syncthreads();
        if (t < HID) {
            float a = bd1[t];
            #pragma unroll
            for (int d = 0; d < ZD; d++) a += dyn[HID + d] * Wd1[d * HID + t];
            dyn[HID + ZD + t] = fmaxf(a, 0.f);    // d1
        }
        __syncthreads();
        for (int u = bid * NT + t; u < UTRI; u += CSZ * NT) {
            int uu = u, rr = 0, rem = N - 1;
            while (uu >= rem) { uu -= rem; rem--; rr++; }
            int cc = rr + 1 + uu;
            float a = bd2[u];
            #pragma unroll 8
            for (int k2 = 0; k2 < HID; k2++)
                a += dyn[HID + ZD + k2] * Wd2[k2 * NUM_LOGITS + u];
            float th  = tanhf(a);
            float sig = 1.f / (1.f + expf(-th));
            g_B[rr * N + cc] = sig;               // B IS symmetric
            g_B[cc * N + rr] = sig;
        }
        if (bid == 0 && t < N) g_B[t * (N + 1)] = 1.f;   // diag = 1
    }
    CSYNC();

    // ---------------- prep: degB, nd, M0, zero row -------------------------
    {
        // col stats: thread (col=r, quarter=g) covers 24 rows, coalesced;
        // valid because B is symmetric (col sums == row sums).
        float s = 0.f, mx = 0.f;
        #pragma unroll 8
        for (int j = 0; j < 24; j++) {
            int row = g * 24 + j;
            float b = g_B[row * N + r];
            s += b;
            if (row != r) mx = fmaxf(mx, b);      // diag excluded from max
        }
        sred[g][r] = s;
        sred[4 + g][r] = mx;
        __syncthreads();
        if (t < N) {
            float db = sred[0][t] + sred[1][t] + sred[2][t] + sred[3][t];
            float m0 = fmaxf(fmaxf(sred[4][t], sred[5][t]),
                             fmaxf(sred[6][t], sred[7][t])) * (1.f / N);
            stmp[t] = db;
            for (int r2 = 0; r2 < RPB; r2++)
                g_M[0][(bid * RPB + r2) * N + t] = m0;    // X0 uniform
            if (bid == 0) { g_M[0][NN + t] = 0.f; g_M[1][NN + t] = 0.f; }
        }
        __syncthreads();
        for (int e = t; e < RPB * N; e += NT) {
            int rw = e / N;
            g_ND[bid * RPB * N + e] =
                1.f / (fabsf(g_degA[bid * RPB + rw] - stmp[e % N]) + 1.f);
        }
    }
}

// ============================= MPM KERNEL ==================================
// (verbatim R10 version — proven correct at rel_err 1.4e-7)
// X_t = F^t(X0)/||F^t(X0)|| (F positively homogeneous): intermediate
// normalizations are redundant; exact uniform rescale every 4 iters controls
// fp32 range; final norm exact.
template <int CSZ>
__global__ void __launch_bounds__(NT2, 1)
mpm_k(float* __restrict__ out)
{
    constexpr int RPB = N / CSZ;
    constexpr int XE  = RPB * N;

    __shared__ __align__(16) float sX[XE];
    __shared__ float sND[XE];
    __shared__ int   snbroff[RPB * DMAX];
    __shared__ int   sdegp[RPB];
    __shared__ float red[24];

    const int t    = threadIdx.x;
    const int bid  = blockIdx.x;
    const int lane = t & 31, wid = t >> 5;
    const int q    = t >> 3;               // M-compute column 0..95
    const int c    = t & 7;                // M-compute l-octant 0..7
    const int gbase = bid * XE;

    for (int e = t; e < XE; e += NT2) {
        sX[e]  = 1.f / N;
        sND[e] = g_ND[gbase + e];
    }
    for (int e = t; e < RPB * DMAX; e += NT2) {
        int rw = e / DMAX, m = e % DMAX;
        int dg = g_deg[bid * RPB + rw];
        dg = (dg > DMAX) ? DMAX : dg;
        snbroff[e] = (m < dg) ? g_nbr[(bid * RPB + rw) * N + m] * N : NN;
        if (m == 0) sdegp[rw] = (dg + 3) & ~3;
    }
    float Breg[12];
    #pragma unroll
    for (int j = 0; j < 12; j++) {
        int l = 12 * c + j;
        Breg[j] = (l == q) ? 0.f : g_B[l * N + q];
    }
    __syncthreads();

    for (int it = 0; it < ITERS; it++) {
        const float* __restrict__ Min  = g_M[it & 1];
        float*       __restrict__ Mout = g_M[(it + 1) & 1];

        float scale = 1.f;
        if (it > 0 && (it & 3) == 0) {
            float p = (lane < CSZ) ? __ldcg(&g_part[lane]) : 0.f;
            p += __shfl_xor_sync(~0u, p, 8);
            p += __shfl_xor_sync(~0u, p, 4);
            p += __shfl_xor_sync(~0u, p, 2);
            p += __shfl_xor_sync(~0u, p, 1);
            scale = rsqrtf(__shfl_sync(~0u, p, 0));
        }
        const bool last = (it == ITERS - 1);
        const bool pub  = ((it & 3) == 3) || last;

        float sq = 0.f;
        for (int e = t; e < XE; e += NT2) {
            int rw = e / 96, col = e % 96;
            float raw = sX[e] * sND[e];
            int dp = sdegp[rw];
            const int* off = &snbroff[rw * DMAX];
            for (int m = 0; m < dp; m += 4) {
                int o0 = off[m], o1 = off[m + 1], o2 = off[m + 2], o3 = off[m + 3];
                raw += __ldcg(&Min[o0 + col]) + __ldcg(&Min[o1 + col])
                     + __ldcg(&Min[o2 + col]) + __ldcg(&Min[o3 + col]);
            }
            float v = raw * scale;
            sX[e] = v;
            if (pub) sq += v * v;
        }
        if (pub) {
            #pragma unroll
            for (int o = 16; o; o >>= 1) sq += __shfl_xor_sync(~0u, sq, o);
            if (lane == 0) red[wid] = sq;
        }
        __syncthreads();
        if (pub && t == 0) {
            float s2 = 0.f;
            #pragma unroll
            for (int w = 0; w < 24; w++) s2 += red[w];
            __stcg(&g_part[bid], s2);
        }

        if (!last) {
            #pragma unroll
            for (int r2 = 0; r2 < RPB; r2++) {
                const float4* xp = (const float4*)&sX[r2 * N + 12 * c];
                float4 x0 = xp[0], x1 = xp[1], x2 = xp[2];
                float ma, mb;
                ma =           Breg[0]  * x0.x;  mb =           Breg[1]  * x0.y;
                ma = fmaxf(ma, Breg[2]  * x0.z); mb = fmaxf(mb, Breg[3]  * x0.w);
                ma = fmaxf(ma, Breg[4]  * x1.x); mb = fmaxf(mb, Breg[5]  * x1.y);
                ma = fmaxf(ma, Breg[6]  * x1.z); mb = fmaxf(mb, Breg[7]  * x1.w);
                ma = fmaxf(ma, Breg[8]  * x2.x); mb = fmaxf(mb, Breg[9]  * x2.y);
                ma = fmaxf(ma, Breg[10] * x2.z); mb = fmaxf(mb, Breg[11] * x2.w);
                float m = fmaxf(ma, mb);
                m = fmaxf(m, __shfl_down_sync(~0u, m, 4));
                m = fmaxf(m, __shfl_down_sync(~0u, m, 2));
                m = fmaxf(m, __shfl_down_sync(~0u, m, 1));
                if (c == 0) __stcg(&Mout[gbase + r2 * N + q], m);
            }
        }
        CSYNC();
    }

    // exact final normalization
    {
        float p = (lane < CSZ) ? __ldcg(&g_part[lane]) : 0.f;
        p += __shfl_xor_sync(~0u, p, 8);
        p += __shfl_xor_sync(~0u, p, 4);
        p += __shfl_xor_sync(~0u, p, 2);
        p += __shfl_xor_sync(~0u, p, 1);
        float os = rsqrtf(__shfl_sync(~0u, p, 0));
        for (int e = t; e < XE; e += NT2)
            out[gbase + e] = sX[e] * os;
    }
}

// ---------------- launch ----------------
extern "C" void kernel_launch(void* const* d_in, const int* in_sizes, int n_in,
                              void* d_out, int out_size) {
    const float* x   = (const float*)d_in[0];
    const int*   ei  = (const int*)  d_in[1];
    const float* adj = (const float*)d_in[2];
    const float* W1  = (const float*)d_in[3];
    // d_in[4] = b1 (cancelled by BN)
    const float* g1  = (const float*)d_in[5];
    const float* be1 = (const float*)d_in[6];
    const float* W2  = (const float*)d_in[7];
    // d_in[8] = b2 (cancelled by BN)
    const float* g2  = (const float*)d_in[9];
    const float* be2 = (const float*)d_in[10];
    const float* Wmu = (const float*)d_in[11];
    const float* bmu = (const float*)d_in[12];
    const float* Wlv = (const float*)d_in[13];
    const float* blv = (const float*)d_in[14];
    const float* Wd1 = (const float*)d_in[15];
    const float* bd1 = (const float*)d_in[16];
    const float* Wd2 = (const float*)d_in[17];
    const float* bd2 = (const float*)d_in[18];
    const float* eps = (const float*)d_in[19];
    float* o = (float*)d_out;

    const size_t sh16 = (size_t)(N * ATS + 2 * 96 * 17) * sizeof(float);  // 50304
    const size_t sh8  = (size_t)(N * ATS + 2 * 96 * 33) * sizeof(float);  // 62592

    cudaFuncSetAttribute(prologue_k<16>, cudaFuncAttributeNonPortableClusterSizeAllowed, 1);
    cudaFuncSetAttribute(mpm_k<16>,      cudaFuncAttributeNonPortableClusterSizeAllowed, 1);
    cudaFuncSetAttribute(prologue_k<16>, cudaFuncAttributeMaxDynamicSharedMemorySize, (int)sh16);
    cudaFuncSetAttribute(prologue_k<8>,  cudaFuncAttributeMaxDynamicSharedMemorySize, (int)sh8);

    cudaLaunchAttribute at16[1];
    at16[0].id = cudaLaunchAttributeClusterDimension;
    at16[0].val.clusterDim = {16, 1, 1};

    cudaLaunchConfig_t cfgP16 = {};
    cfgP16.gridDim = dim3(16, 1, 1);
    cfgP16.blockDim = dim3(NT, 1, 1);
    cfgP16.dynamicSmemBytes = sh16;
    cfgP16.attrs = at16;  cfgP16.numAttrs = 1;

    cudaLaunchConfig_t cfgM16 = {};
    cfgM16.gridDim = dim3(16, 1, 1);
    cfgM16.blockDim = dim3(NT2, 1, 1);
    cfgM16.attrs = at16;  cfgM16.numAttrs = 1;

    int np = 0, nm = 0;
    cudaError_t e1 = cudaOccupancyMaxActiveClusters(&np, prologue_k<16>, &cfgP16);
    cudaError_t e2 = cudaOccupancyMaxActiveClusters(&nm, mpm_k<16>, &cfgM16);
    if (e1 != cudaSuccess || e2 != cudaSuccess) { (void)cudaGetLastError(); np = nm = 0; }

    if (np >= 1 && nm >= 1) {
        cudaLaunchKernelEx(&cfgP16, prologue_k<16>,
            x, ei, adj, W1, g1, be1, W2, g2, be2,
            Wmu, bmu, Wlv, blv, Wd1, bd1, Wd2, bd2, eps);
        cudaLaunchKernelEx(&cfgM16, mpm_k<16>, o);
    } else {
        cudaLaunchAttribute at8[1];
        at8[0].id = cudaLaunchAttributeClusterDimension;
        at8[0].val.clusterDim = {8, 1, 1};
        cudaLaunchConfig_t cfgP8 = {};
        cfgP8.gridDim = dim3(8, 1, 1);
        cfgP8.blockDim = dim3(NT, 1, 1);
        cfgP8.dynamicSmemBytes = sh8;
        cfgP8.attrs = at8;  cfgP8.numAttrs = 1;
        cudaLaunchConfig_t cfgM8 = {};
        cfgM8.gridDim = dim3(8, 1, 1);
        cfgM8.blockDim = dim3(NT2, 1, 1);
        cfgM8.attrs = at8;  cfgM8.numAttrs = 1;
        cudaLaunchKernelEx(&cfgP8, prologue_k<8>,
            x, ei, adj, W1, g1, be1, W2, g2, be2,
            Wmu, bmu, Wlv, blv, Wd1, bd1, Wd2, bd2, eps);
        cudaLaunchKernelEx(&cfgM8, mpm_k<8>, o);
    }
}

// round 14
// speedup vs baseline: 1.7293x; 1.0345x over previous
#include <cuda_runtime.h>
#include <math.h>

#define N        96
#define NT       384     // prologue threads per CTA
#define NT2      768     // MPM threads per CTA (24 warps)
#define NDEC     152     // decoder CTAs: 152*30 == UTRI exactly
#define NN       9216
#define ATS      97      // padded stride for transposed A_norm in smem
#define IN_DIM   64
#define HID      256
#define ZD       64
#define E        1024
#define NUM_LOGITS 4656
#define ITERS    50
#define UTRI     4560
#define DMAX     32      // padded neighbor-list capacity

// ---------------- device scratch (no allocations allowed) ----------------
__device__ float g_Anorm[NN];
__device__ float g_Ht[N * HID];       // layer-1 activations, TRANSPOSED
__device__ float g_gv[HID];
__device__ float g_B[NN];
__device__ float g_degA[N];
__device__ int   g_deg[N];
__device__ int   g_nbr[NN];
__device__ float g_M[2][NN + N];      // +1 zero row for padded neighbors
__device__ float g_part[16];          // per-CTA sum-of-squares partials

#define C_ARRIVE() asm volatile("barrier.cluster.arrive.aligned;" ::: "memory")
#define C_WAIT()   asm volatile("barrier.cluster.wait.aligned;"   ::: "memory")
#define CSYNC() do { C_ARRIVE(); C_WAIT(); } while (0)

// =========================== PROLOGUE KERNEL ===============================
// GCN-only now (decoder/prep moved out). Column-distributed; A_norm staged
// TRANSPOSED in smem (it is NOT symmetric: edge_index is directed).
template <int CSZ>
__global__ void __launch_bounds__(NT, 1)
prologue_k(
    const float* __restrict__ x,   const int* __restrict__ ei,
    const float* __restrict__ adj,
    const float* __restrict__ W1,  const float* __restrict__ g1,  const float* __restrict__ be1,
    const float* __restrict__ W2,  const float* __restrict__ g2,  const float* __restrict__ be2)
{
    constexpr int CPC = HID / CSZ;
    constexpr int CW  = CPC / 4;
    constexpr int STP = CPC + 1;

    extern __shared__ float sm[];
    float* dyn = sm;                   // 96*ATS (adj linear / x / A_norm^T)
    float* sT  = sm + N * ATS;         // 96*STP
    float* sP  = sT + 96 * STP;        // 96*STP

    __shared__ float stmp[N];

    const int t    = threadIdx.x;
    const int bid  = blockIdx.x;
    const int lane = t & 31, wid = t >> 5;
    const int r    = t % 96, g = t / 96;
    const int lc   = g * CW;
    const int gcol = bid * CPC + lc;

    // ---------------- P1: adjacency (CTA0) + gemm1 (all CTAs) -------------
    if (bid == 0) {
        for (int i = t; i < NN; i += NT) dyn[i] = 0.f;
        __syncthreads();
        for (int e = t; e < E; e += NT)
            dyn[ei[e] * N + ei[E + e]] = 1.f;     // identical-value races OK
        __syncthreads();
        if (t < N) dyn[t * (N + 1)] = 1.f;        // A = max(A, I)
        __syncthreads();
        for (int rr = wid; rr < N; rr += 12) {    // ROW sums (directed A!)
            float s = dyn[rr * N + lane] + dyn[rr * N + lane + 32]
                    + dyn[rr * N + lane + 64];
            #pragma unroll
            for (int o = 16; o; o >>= 1) s += __shfl_xor_sync(~0u, s, o);
            if (lane == 0) stmp[rr] = rsqrtf(s);
        }
        __syncthreads();
        for (int i = t; i < NN; i += NT) {
            int rr = i / N, cc = i - rr * N;
            g_Anorm[i] = dyn[i] * stmp[rr] * stmp[cc];
        }
        if (t < N) {                 // adj_gt IS symmetric -> coalesced col read
            float s = 0.f; int cnt = 0;
            #pragma unroll 4
            for (int j = 0; j < N; j++) {
                float v = adj[j * N + t];
                s += v;
                if (v > 0.5f) g_nbr[t * N + cnt++] = j;
            }
            g_degA[t] = s + 1.f;                  // Agt diag forced to 1
            g_deg[t]  = cnt;
        }
        __syncthreads();
    }
    // stage x transposed+padded
    for (int i = t; i < N * IN_DIM; i += NT) {
        int rr = i >> 6, k = i & 63;
        dyn[k * ATS + rr] = x[i];
    }
    __syncthreads();
    {   // T1cols = x @ W1 (bias b1 exactly cancelled by BN)
        float acc[CW];
        #pragma unroll
        for (int c = 0; c < CW; c++) acc[c] = 0.f;
        #pragma unroll 8
        for (int k = 0; k < IN_DIM; k++) {
            float xv = dyn[k * ATS + r];
            #pragma unroll
            for (int c4 = 0; c4 < CW / 4; c4++) {
                float4 w = *(const float4*)&W1[k * HID + gcol + 4 * c4];
                acc[4*c4+0] += xv * w.x; acc[4*c4+1] += xv * w.y;
                acc[4*c4+2] += xv * w.z; acc[4*c4+3] += xv * w.w;
            }
        }
        #pragma unroll
        for (int c = 0; c < CW; c++) sT[r * STP + lc + c] = acc[c];
    }
    CSYNC();

    // A_norm^T staged: dyn[cc*ATS+rr] = A_norm[rr][cc]
    for (int i = t; i < NN; i += NT) {
        int rr = i / N, cc = i - rr * N;
        dyn[cc * ATS + rr] = g_Anorm[i];
    }
    __syncthreads();

    auto gcnbn = [&](const float* gamma, const float* beta, bool writeH, bool dogv) {
        float acc[CW];
        #pragma unroll
        for (int c = 0; c < CW; c++) acc[c] = 0.f;
        #pragma unroll 4
        for (int j = 0; j < N; j++) {
            float a = dyn[j * ATS + r];           // A_norm[r][j] (true row)
            #pragma unroll
            for (int c = 0; c < CW; c++)
                acc[c] += a * sT[j * STP + lc + c];
        }
        #pragma unroll
        for (int c = 0; c < CW; c++) sP[r * STP + lc + c] = acc[c];
        __syncthreads();
        for (int cc = wid; cc < CPC; cc += 12) {
            int col = bid * CPC + cc;
            float v0 = sP[lane * STP + cc];
            float v1 = sP[(lane + 32) * STP + cc];
            float v2 = sP[(lane + 64) * STP + cc];
            float s = v0 + v1 + v2, qd = v0*v0 + v1*v1 + v2*v2;
            #pragma unroll
            for (int o = 16; o; o >>= 1) {
                s  += __shfl_xor_sync(~0u, s, o);
                qd += __shfl_xor_sync(~0u, qd, o);
            }
            float m   = s * (1.f / N);
            float var = qd * (1.f / N) - m * m;
            float inv = rsqrtf(var + 1e-5f) * gamma[col];
            float bb  = beta[col];
            float h0 = fmaxf((v0 - m) * inv + bb, 0.f);
            float h1 = fmaxf((v1 - m) * inv + bb, 0.f);
            float h2 = fmaxf((v2 - m) * inv + bb, 0.f);
            if (writeH) {
                g_Ht[col * 96 + lane]      = h0;
                g_Ht[col * 96 + lane + 32] = h1;
                g_Ht[col * 96 + lane + 64] = h2;
            }
            if (dogv) {
                float gs = h0 + h1 + h2;
                #pragma unroll
                for (int o = 16; o; o >>= 1) gs += __shfl_xor_sync(~0u, gs, o);
                if (lane == 0) g_gv[col] = gs * (1.f / N);
            }
        }
    };

    gcnbn(g1, be1, true, false);     // layer 1 -> g_Ht
    CSYNC();

    {   // gemm2: T = H @ W2
        float acc[CW];
        #pragma unroll
        for (int c = 0; c < CW; c++) acc[c] = 0.f;
        #pragma unroll 4
        for (int k = 0; k < HID; k++) {
            float hv = g_Ht[k * 96 + r];
            #pragma unroll
            for (int c4 = 0; c4 < CW / 4; c4++) {
                float4 w = *(const float4*)&W2[k * HID + gcol + 4 * c4];
                acc[4*c4+0] += hv * w.x; acc[4*c4+1] += hv * w.y;
                acc[4*c4+2] += hv * w.z; acc[4*c4+3] += hv * w.w;
            }
        }
        __syncthreads();
        #pragma unroll
        for (int c = 0; c < CW; c++) sT[r * STP + lc + c] = acc[c];
    }
    __syncthreads();
    gcnbn(g2, be2, false, true);     // layer 2 -> g_gv (kernel end = sync)
}

// ============================ DECODER KERNEL ===============================
// Full-chip grid (152 CTAs, no cluster). Each CTA redundantly computes the
// VAE head (z, d1) and 30 upper-tri B entries (152*30 == UTRI).
__global__ void __launch_bounds__(256, 1)
decoder_k(const float* __restrict__ Wmu, const float* __restrict__ bmu,
          const float* __restrict__ Wlv, const float* __restrict__ blv,
          const float* __restrict__ Wd1, const float* __restrict__ bd1,
          const float* __restrict__ Wd2, const float* __restrict__ bd2,
          const float* __restrict__ eps)
{
    __shared__ float sgv[HID];
    __shared__ float sz[ZD];
    __shared__ float sd1[HID];
    __shared__ float smu[4][ZD], slv[4][ZD];
    __shared__ float spart[8][32];

    const int t   = threadIdx.x;
    const int bid = blockIdx.x;
    const int w   = t >> 5, lane = t & 31;

    sgv[t] = g_gv[t];
    __syncthreads();

    // mu/lv: 4-way k-split, 64 iters each
    {
        int gg = t >> 6, cI = t & 63;
        float pm = 0.f, pl = 0.f;
        #pragma unroll 8
        for (int k = gg * 64; k < gg * 64 + 64; k++) {
            float gv = sgv[k];
            pm += gv * Wmu[k * ZD + cI];
            pl += gv * Wlv[k * ZD + cI];
        }
        smu[gg][cI] = pm; slv[gg][cI] = pl;
    }
    __syncthreads();
    if (t < ZD) {
        float mu = bmu[t] + smu[0][t] + smu[1][t] + smu[2][t] + smu[3][t];
        float lv = blv[t] + slv[0][t] + slv[1][t] + slv[2][t] + slv[3][t];
        lv = fminf(fmaxf(lv, -4.f), 4.f);
        sz[t] = mu + eps[t] * expf(0.5f * lv);
    }
    __syncthreads();
    {   // d1 = relu(z @ Wd1 + bd1)
        float a = bd1[t];
        #pragma unroll 8
        for (int d = 0; d < ZD; d++) a += sz[d] * Wd1[d * HID + t];
        sd1[t] = fmaxf(a, 0.f);
    }
    __syncthreads();

    // 30 entries: warp w covers k2 [32w, 32w+32); lane e < 30 -> entry
    {
        float p = 0.f;
        if (lane < 30) {
            int u = bid * 30 + lane;
            #pragma unroll 8
            for (int k2 = w * 32; k2 < w * 32 + 32; k2++)
                p += sd1[k2] * Wd2[k2 * NUM_LOGITS + u];
        }
        spart[w][lane] = p;
    }
    __syncthreads();
    if (t < 30) {
        int u = bid * 30 + t;
        float a = bd2[u];
        #pragma unroll
        for (int w2 = 0; w2 < 8; w2++) a += spart[w2][t];
        int uu = u, rr = 0, rem = N - 1;
        while (uu >= rem) { uu -= rem; rem--; rr++; }
        int cc = rr + 1 + uu;
        float th  = tanhf(a);
        float sig = 1.f / (1.f + expf(-th));
        g_B[rr * N + cc] = sig;               // B IS symmetric
        g_B[cc * N + rr] = sig;
    }
    if (bid == 0 && t < N) g_B[t * (N + 1)] = 1.f;   // diag = 1
}

// ============================= MPM KERNEL ==================================
// Startup computes B stats / nd / neighbor lists locally (B written by
// decoder_k; kernel boundary = full sync). M0 is never materialized: all M0
// rows are identical, so iteration 0 uses deg[i]*sm0[col] from smem.
// F positively homogeneous: exact uniform rescale every 4 iters controls
// fp32 range; final norm exact.
template <int CSZ>
__global__ void __launch_bounds__(NT2, 1)
mpm_k(float* __restrict__ out)
{
    constexpr int RPB = N / CSZ;
    constexpr int XE  = RPB * N;

    __shared__ __align__(16) float sX[XE];
    __shared__ float sND[XE];
    __shared__ float sdb[N];              // B column sums (== row sums)
    __shared__ float sm0[N];              // max_{l!=k} B[k,l] / N
    __shared__ int   snbroff[RPB * DMAX];
    __shared__ int   sdegp[RPB];          // padded degree (mult of 4)
    __shared__ int   sdegr[RPB];          // real degree
    __shared__ float red[24];

    const int t    = threadIdx.x;
    const int bid  = blockIdx.x;
    const int lane = t & 31, wid = t >> 5;
    const int q    = t >> 3;
    const int c    = t & 7;
    const int gbase = bid * XE;

    // ---- startup: B row stats (coalesced; B symmetric -> col stats) -------
    for (int row = wid; row < N; row += 24) {
        float b0 = g_B[row * N + lane];
        float b1 = g_B[row * N + lane + 32];
        float b2 = g_B[row * N + lane + 64];
        float s  = b0 + b1 + b2;
        float m  = fmaxf(fmaxf((lane == row) ? 0.f : b0,
                               (lane + 32 == row) ? 0.f : b1),
                               (lane + 64 == row) ? 0.f : b2);
        #pragma unroll
        for (int o = 16; o; o >>= 1) {
            s = s + __shfl_xor_sync(~0u, s, o);
            m = fmaxf(m, __shfl_xor_sync(~0u, m, o));
        }
        if (lane == 0) { sdb[row] = s; sm0[row] = m * (1.f / N); }
    }
    for (int e = t; e < RPB * DMAX; e += NT2) {
        int rw = e / DMAX, m = e % DMAX;
        int dg = g_deg[bid * RPB + rw];
        dg = (dg > DMAX) ? DMAX : dg;
        snbroff[e] = (m < dg) ? g_nbr[(bid * RPB + rw) * N + m] * N : NN;
        if (m == 0) { sdegp[rw] = (dg + 3) & ~3; sdegr[rw] = dg; }
    }
    if (t < N) { __stcg(&g_M[0][NN + t], 0.f); __stcg(&g_M[1][NN + t], 0.f); }
    float Breg[12];
    #pragma unroll
    for (int j = 0; j < 12; j++) {
        int l = 12 * c + j;
        Breg[j] = (l == q) ? 0.f : g_B[l * N + q];
    }
    __syncthreads();
    for (int e = t; e < XE; e += NT2) {
        int rw = e / 96;
        sX[e]  = 1.f / N;
        sND[e] = 1.f / (fabsf(g_degA[bid * RPB + rw] - sdb[e % 96]) + 1.f);
    }
    __syncthreads();

    for (int it = 0; it < ITERS; it++) {
        const float* __restrict__ Min  = g_M[it & 1];
        float*       __restrict__ Mout = g_M[(it + 1) & 1];

        float scale = 1.f;
        if (it > 0 && (it & 3) == 0) {
            float p = (lane < CSZ) ? __ldcg(&g_part[lane]) : 0.f;
            p += __shfl_xor_sync(~0u, p, 8);
            p += __shfl_xor_sync(~0u, p, 4);
            p += __shfl_xor_sync(~0u, p, 2);
            p += __shfl_xor_sync(~0u, p, 1);
            scale = rsqrtf(__shfl_sync(~0u, p, 0));
        }
        const bool last = (it == ITERS - 1);
        const bool pub  = ((it & 3) == 3) || last;

        float sq = 0.f;
        for (int e = t; e < XE; e += NT2) {
            int rw = e / 96, col = e % 96;
            float raw = sX[e] * sND[e];
            if (it == 0) {
                raw += (float)sdegr[rw] * sm0[col];   // all M0 rows identical
            } else {
                int dp = sdegp[rw];
                const int* off = &snbroff[rw * DMAX];
                for (int m = 0; m < dp; m += 4) {
                    int o0 = off[m], o1 = off[m + 1], o2 = off[m + 2], o3 = off[m + 3];
                    raw += __ldcg(&Min[o0 + col]) + __ldcg(&Min[o1 + col])
                         + __ldcg(&Min[o2 + col]) + __ldcg(&Min[o3 + col]);
                }
            }
            float v = raw * scale;
            sX[e] = v;
            if (pub) sq += v * v;
        }
        if (pub) {
            #pragma unroll
            for (int o = 16; o; o >>= 1) sq += __shfl_xor_sync(~0u, sq, o);
            if (lane == 0) red[wid] = sq;
        }
        __syncthreads();
        if (pub && t == 0) {
            float s2 = 0.f;
            #pragma unroll
            for (int w = 0; w < 24; w++) s2 += red[w];
            __stcg(&g_part[bid], s2);
        }

        if (!last) {
            #pragma unroll
            for (int r2 = 0; r2 < RPB; r2++) {
                const float4* xp = (const float4*)&sX[r2 * N + 12 * c];
                float4 x0 = xp[0], x1 = xp[1], x2 = xp[2];
                float ma, mb;
                ma =           Breg[0]  * x0.x;  mb =           Breg[1]  * x0.y;
                ma = fmaxf(ma, Breg[2]  * x0.z); mb = fmaxf(mb, Breg[3]  * x0.w);
                ma = fmaxf(ma, Breg[4]  * x1.x); mb = fmaxf(mb, Breg[5]  * x1.y);
                ma = fmaxf(ma, Breg[6]  * x1.z); mb = fmaxf(mb, Breg[7]  * x1.w);
                ma = fmaxf(ma, Breg[8]  * x2.x); mb = fmaxf(mb, Breg[9]  * x2.y);
                ma = fmaxf(ma, Breg[10] * x2.z); mb = fmaxf(mb, Breg[11] * x2.w);
                float m = fmaxf(ma, mb);
                m = fmaxf(m, __shfl_down_sync(~0u, m, 4));
                m = fmaxf(m, __shfl_down_sync(~0u, m, 2));
                m = fmaxf(m, __shfl_down_sync(~0u, m, 1));
                if (c == 0) __stcg(&Mout[gbase + r2 * N + q], m);
            }
        }
        CSYNC();
    }

    // exact final normalization
    {
        float p = (lane < CSZ) ? __ldcg(&g_part[lane]) : 0.f;
        p += __shfl_xor_sync(~0u, p, 8);
        p += __shfl_xor_sync(~0u, p, 4);
        p += __shfl_xor_sync(~0u, p, 2);
        p += __shfl_xor_sync(~0u, p, 1);
        float os = rsqrtf(__shfl_sync(~0u, p, 0));
        for (int e = t; e < XE; e += NT2)
            out[gbase + e] = sX[e] * os;
    }
}

// ---------------- launch ----------------
extern "C" void kernel_launch(void* const* d_in, const int* in_sizes, int n_in,
                              void* d_out, int out_size) {
    const float* x   = (const float*)d_in[0];
    const int*   ei  = (const int*)  d_in[1];
    const float* adj = (const float*)d_in[2];
    const float* W1  = (const float*)d_in[3];
    // d_in[4] = b1 (cancelled by BN)
    const float* g1  = (const float*)d_in[5];
    const float* be1 = (const float*)d_in[6];
    const float* W2  = (const float*)d_in[7];
    // d_in[8] = b2 (cancelled by BN)
    const float* g2  = (const float*)d_in[9];
    const float* be2 = (const float*)d_in[10];
    const float* Wmu = (const float*)d_in[11];
    const float* bmu = (const float*)d_in[12];
    const float* Wlv = (const float*)d_in[13];
    const float* blv = (const float*)d_in[14];
    const float* Wd1 = (const float*)d_in[15];
    const float* bd1 = (const float*)d_in[16];
    const float* Wd2 = (const float*)d_in[17];
    const float* bd2 = (const float*)d_in[18];
    const float* eps = (const float*)d_in[19];
    float* o = (float*)d_out;

    const size_t sh16 = (size_t)(N * ATS + 2 * 96 * 17) * sizeof(float);
    const size_t sh8  = (size_t)(N * ATS + 2 * 96 * 33) * sizeof(float);

    cudaFuncSetAttribute(prologue_k<16>, cudaFuncAttributeNonPortableClusterSizeAllowed, 1);
    cudaFuncSetAttribute(mpm_k<16>,      cudaFuncAttributeNonPortableClusterSizeAllowed, 1);
    cudaFuncSetAttribute(prologue_k<16>, cudaFuncAttributeMaxDynamicSharedMemorySize, (int)sh16);
    cudaFuncSetAttribute(prologue_k<8>,  cudaFuncAttributeMaxDynamicSharedMemorySize, (int)sh8);

    cudaLaunchAttribute at16[1];
    at16[0].id = cudaLaunchAttributeClusterDimension;
    at16[0].val.clusterDim = {16, 1, 1};

    cudaLaunchConfig_t cfgP16 = {};
    cfgP16.gridDim = dim3(16, 1, 1);
    cfgP16.blockDim = dim3(NT, 1, 1);
    cfgP16.dynamicSmemBytes = sh16;
    cfgP16.attrs = at16;  cfgP16.numAttrs = 1;

    cudaLaunchConfig_t cfgM16 = {};
    cfgM16.gridDim = dim3(16, 1, 1);
    cfgM16.blockDim = dim3(NT2, 1, 1);
    cfgM16.attrs = at16;  cfgM16.numAttrs = 1;

    int np = 0, nm = 0;
    cudaError_t e1 = cudaOccupancyMaxActiveClusters(&np, prologue_k<16>, &cfgP16);
    cudaError_t e2 = cudaOccupancyMaxActiveClusters(&nm, mpm_k<16>, &cfgM16);
    if (e1 != cudaSuccess || e2 != cudaSuccess) { (void)cudaGetLastError(); np = nm = 0; }

    if (np >= 1 && nm >= 1) {
        cudaLaunchKernelEx(&cfgP16, prologue_k<16>,
            x, ei, adj, W1, g1, be1, W2, g2, be2);
        decoder_k<<<NDEC, 256>>>(Wmu, bmu, Wlv, blv, Wd1, bd1, Wd2, bd2, eps);
        cudaLaunchKernelEx(&cfgM16, mpm_k<16>, o);
    } else {
        cudaLaunchAttribute at8[1];
        at8[0].id = cudaLaunchAttributeClusterDimension;
        at8[0].val.clusterDim = {8, 1, 1};
        cudaLaunchConfig_t cfgP8 = {};
        cfgP8.gridDim = dim3(8, 1, 1);
        cfgP8.blockDim = dim3(NT, 1, 1);
        cfgP8.dynamicSmemBytes = sh8;
        cfgP8.attrs = at8;  cfgP8.numAttrs = 1;
        cudaLaunchConfig_t cfgM8 = {};
        cfgM8.gridDim = dim3(8, 1, 1);
        cfgM8.blockDim = dim3(NT2, 1, 1);
        cfgM8.attrs = at8;  cfgM8.numAttrs = 1;
        cudaLaunchKernelEx(&cfgP8, prologue_k<8>,
            x, ei, adj, W1, g1, be1, W2, g2, be2);
        decoder_k<<<NDEC, 256>>>(Wmu, bmu, Wlv, blv, Wd1, bd1, Wd2, bd2, eps);
        cudaLaunchKernelEx(&cfgM8, mpm_k<8>, o);
    }
}

// round 15
// speedup vs baseline: 1.7811x; 1.0300x over previous
#include <cuda_runtime.h>
#include <math.h>

#define N        96
#define NT       384     // prologue threads per CTA
#define NT2      768     // MPM threads per CTA (24 warps)
#define NDEC     148     // decoder CTAs (one full wave); 148*31 >= UTRI
#define DU       31      // upper-tri entries per decoder CTA
#define NN       9216
#define ATS      97      // padded stride for transposed A_norm in smem
#define IN_DIM   64
#define HID      256
#define ZD       64
#define E        1024
#define NUM_LOGITS 4656
#define ITERS    50
#define UTRI     4560
#define DMAX     32      // padded neighbor-list capacity

#define PREF_L2(p) asm volatile("prefetch.global.L2 [%0];" :: "l"(p))

// ---------------- device scratch (no allocations allowed) ----------------
__device__ float g_Anorm[NN];
__device__ float g_Ht[N * HID];       // layer-1 activations, TRANSPOSED
__device__ float g_gv[HID];
__device__ float g_B[NN];
__device__ float g_degA[N];
__device__ int   g_deg[N];
__device__ int   g_nbr[NN];
__device__ float g_M[2][NN + N];      // +1 zero row for padded neighbors
__device__ float g_part[16];          // per-CTA sum-of-squares partials

#define C_ARRIVE() asm volatile("barrier.cluster.arrive.aligned;" ::: "memory")
#define C_WAIT()   asm volatile("barrier.cluster.wait.aligned;"   ::: "memory")
#define CSYNC() do { C_ARRIVE(); C_WAIT(); } while (0)

// =========================== PROLOGUE KERNEL ===============================
// GCN-only. Column-distributed; A_norm staged TRANSPOSED in smem (it is NOT
// symmetric: edge_index is directed). W1/W2 slices L2-prefetched up front.
template <int CSZ>
__global__ void __launch_bounds__(NT, 1)
prologue_k(
    const float* __restrict__ x,   const int* __restrict__ ei,
    const float* __restrict__ W1,  const float* __restrict__ g1,  const float* __restrict__ be1,
    const float* __restrict__ W2,  const float* __restrict__ g2,  const float* __restrict__ be2)
{
    constexpr int CPC = HID / CSZ;
    constexpr int CW  = CPC / 4;
    constexpr int STP = CPC + 1;

    extern __shared__ float sm[];
    float* dyn = sm;                   // 96*ATS (adj linear / x / A_norm^T)
    float* sT  = sm + N * ATS;         // 96*STP
    float* sP  = sT + 96 * STP;        // 96*STP

    __shared__ float stmp[N];

    const int t    = threadIdx.x;
    const int bid  = blockIdx.x;
    const int lane = t & 31, wid = t >> 5;
    const int r    = t % 96, g = t / 96;
    const int lc   = g * CW;
    const int gcol = bid * CPC + lc;

    // ---- warm L2 with this CTA's weight slices (fire-and-forget) ---------
    if (t < IN_DIM) PREF_L2(&W1[t * HID + bid * CPC]);
    if (t < HID)    PREF_L2(&W2[t * HID + bid * CPC]);

    // ---------------- P1: adjacency A_norm (CTA0) + gemm1 (all CTAs) ------
    if (bid == 0) {
        for (int i = t; i < NN; i += NT) dyn[i] = 0.f;
        __syncthreads();
        for (int e = t; e < E; e += NT)
            dyn[ei[e] * N + ei[E + e]] = 1.f;     // identical-value races OK
        __syncthreads();
        if (t < N) dyn[t * (N + 1)] = 1.f;        // A = max(A, I)
        __syncthreads();
        for (int rr = wid; rr < N; rr += 12) {    // ROW sums (directed A!)
            float s = dyn[rr * N + lane] + dyn[rr * N + lane + 32]
                    + dyn[rr * N + lane + 64];
            #pragma unroll
            for (int o = 16; o; o >>= 1) s += __shfl_xor_sync(~0u, s, o);
            if (lane == 0) stmp[rr] = rsqrtf(s);
        }
        __syncthreads();
        for (int i = t; i < NN; i += NT) {
            int rr = i / N, cc = i - rr * N;
            g_Anorm[i] = dyn[i] * stmp[rr] * stmp[cc];
        }
        __syncthreads();
    }
    // stage x transposed+padded
    for (int i = t; i < N * IN_DIM; i += NT) {
        int rr = i >> 6, k = i & 63;
        dyn[k * ATS + rr] = x[i];
    }
    __syncthreads();
    {   // T1cols = x @ W1 (bias b1 exactly cancelled by BN)
        float acc[CW];
        #pragma unroll
        for (int c = 0; c < CW; c++) acc[c] = 0.f;
        #pragma unroll 8
        for (int k = 0; k < IN_DIM; k++) {
            float xv = dyn[k * ATS + r];
            #pragma unroll
            for (int c4 = 0; c4 < CW / 4; c4++) {
                float4 w = *(const float4*)&W1[k * HID + gcol + 4 * c4];
                acc[4*c4+0] += xv * w.x; acc[4*c4+1] += xv * w.y;
                acc[4*c4+2] += xv * w.z; acc[4*c4+3] += xv * w.w;
            }
        }
        #pragma unroll
        for (int c = 0; c < CW; c++) sT[r * STP + lc + c] = acc[c];
    }
    CSYNC();

    // A_norm^T staged: dyn[cc*ATS+rr] = A_norm[rr][cc]
    for (int i = t; i < NN; i += NT) {
        int rr = i / N, cc = i - rr * N;
        dyn[cc * ATS + rr] = g_Anorm[i];
    }
    __syncthreads();

    auto gcnbn = [&](const float* gamma, const float* beta, bool writeH, bool dogv) {
        float acc[CW];
        #pragma unroll
        for (int c = 0; c < CW; c++) acc[c] = 0.f;
        #pragma unroll 4
        for (int j = 0; j < N; j++) {
            float a = dyn[j * ATS + r];           // A_norm[r][j] (true row)
            #pragma unroll
            for (int c = 0; c < CW; c++)
                acc[c] += a * sT[j * STP + lc + c];
        }
        #pragma unroll
        for (int c = 0; c < CW; c++) sP[r * STP + lc + c] = acc[c];
        __syncthreads();
        for (int cc = wid; cc < CPC; cc += 12) {
            int col = bid * CPC + cc;
            float v0 = sP[lane * STP + cc];
            float v1 = sP[(lane + 32) * STP + cc];
            float v2 = sP[(lane + 64) * STP + cc];
            float s = v0 + v1 + v2, qd = v0*v0 + v1*v1 + v2*v2;
            #pragma unroll
            for (int o = 16; o; o >>= 1) {
                s  += __shfl_xor_sync(~0u, s, o);
                qd += __shfl_xor_sync(~0u, qd, o);
            }
            float m   = s * (1.f / N);
            float var = qd * (1.f / N) - m * m;
            float inv = rsqrtf(var + 1e-5f) * gamma[col];
            float bb  = beta[col];
            float h0 = fmaxf((v0 - m) * inv + bb, 0.f);
            float h1 = fmaxf((v1 - m) * inv + bb, 0.f);
            float h2 = fmaxf((v2 - m) * inv + bb, 0.f);
            if (writeH) {
                g_Ht[col * 96 + lane]      = h0;
                g_Ht[col * 96 + lane + 32] = h1;
                g_Ht[col * 96 + lane + 64] = h2;
            }
            if (dogv) {
                float gs = h0 + h1 + h2;
                #pragma unroll
                for (int o = 16; o; o >>= 1) gs += __shfl_xor_sync(~0u, gs, o);
                if (lane == 0) g_gv[col] = gs * (1.f / N);
            }
        }
    };

    gcnbn(g1, be1, true, false);     // layer 1 -> g_Ht
    CSYNC();

    {   // gemm2: T = H @ W2 (W2 slice already L2-warm)
        float acc[CW];
        #pragma unroll
        for (int c = 0; c < CW; c++) acc[c] = 0.f;
        #pragma unroll 8
        for (int k = 0; k < HID; k++) {
            float hv = g_Ht[k * 96 + r];
            #pragma unroll
            for (int c4 = 0; c4 < CW / 4; c4++) {
                float4 w = *(const float4*)&W2[k * HID + gcol + 4 * c4];
                acc[4*c4+0] += hv * w.x; acc[4*c4+1] += hv * w.y;
                acc[4*c4+2] += hv * w.z; acc[4*c4+3] += hv * w.w;
            }
        }
        __syncthreads();
        #pragma unroll
        for (int c = 0; c < CW; c++) sT[r * STP + lc + c] = acc[c];
    }
    __syncthreads();
    gcnbn(g2, be2, false, true);     // layer 2 -> g_gv (kernel end = sync)
}

// ============================ DECODER KERNEL ===============================
// Full-chip grid (148 CTAs, one wave, no cluster). Each CTA redundantly
// computes the VAE head and 31 upper-tri B entries. CTA 147 (3 entries only)
// also builds the adj_gt neighbor CSR (ballot compaction) for mpm_k.
__global__ void __launch_bounds__(256, 1)
decoder_k(const float* __restrict__ adj,
          const float* __restrict__ Wmu, const float* __restrict__ bmu,
          const float* __restrict__ Wlv, const float* __restrict__ blv,
          const float* __restrict__ Wd1, const float* __restrict__ bd1,
          const float* __restrict__ Wd2, const float* __restrict__ bd2,
          const float* __restrict__ eps)
{
    __shared__ float sgv[HID];
    __shared__ float sz[ZD];
    __shared__ float sd1[HID];
    __shared__ float smu[4][ZD], slv[4][ZD];
    __shared__ float spart[8][32];

    const int t   = threadIdx.x;
    const int bid = blockIdx.x;
    const int w   = t >> 5, lane = t & 31;

    // warm L2 with this CTA's Wd2 columns (124B per k2 row)
    {
        const float* p = &Wd2[t * NUM_LOGITS + bid * DU];
        PREF_L2(p);
        PREF_L2(p + 24);
    }

    // CTA 147: build neighbor CSR from adj_gt (warp ballot compaction)
    if (bid == NDEC - 1) {
        for (int r = w; r < N; r += 8) {
            float a0 = adj[r * N + lane];
            float a1 = adj[r * N + 32 + lane];
            float a2 = adj[r * N + 64 + lane];
            unsigned m0 = __ballot_sync(~0u, a0 > 0.5f);
            unsigned m1 = __ballot_sync(~0u, a1 > 0.5f);
            unsigned m2 = __ballot_sync(~0u, a2 > 0.5f);
            int c0 = __popc(m0), c1 = __popc(m1);
            unsigned lt = (1u << lane) - 1u;
            if (a0 > 0.5f) g_nbr[r * N + __popc(m0 & lt)] = lane;
            if (a1 > 0.5f) g_nbr[r * N + c0 + __popc(m1 & lt)] = lane + 32;
            if (a2 > 0.5f) g_nbr[r * N + c0 + c1 + __popc(m2 & lt)] = lane + 64;
            if (lane == 0) {
                int dg = c0 + c1 + __popc(m2);
                g_deg[r]  = dg;
                g_degA[r] = (float)dg + 1.f;      // Agt diag forced to 1
            }
        }
    }

    sgv[t] = g_gv[t];
    __syncthreads();

    // mu/lv: 4-way k-split
    {
        int gg = t >> 6, cI = t & 63;
        float pm = 0.f, pl = 0.f;
        #pragma unroll 8
        for (int k = gg * 64; k < gg * 64 + 64; k++) {
            float gv = sgv[k];
            pm += gv * Wmu[k * ZD + cI];
            pl += gv * Wlv[k * ZD + cI];
        }
        smu[gg][cI] = pm; slv[gg][cI] = pl;
    }
    __syncthreads();
    if (t < ZD) {
        float mu = bmu[t] + smu[0][t] + smu[1][t] + smu[2][t] + smu[3][t];
        float lv = blv[t] + slv[0][t] + slv[1][t] + slv[2][t] + slv[3][t];
        lv = fminf(fmaxf(lv, -4.f), 4.f);
        sz[t] = mu + eps[t] * expf(0.5f * lv);
    }
    __syncthreads();
    {   // d1 = relu(z @ Wd1 + bd1)
        float a = bd1[t];
        #pragma unroll 8
        for (int d = 0; d < ZD; d++) a += sz[d] * Wd1[d * HID + t];
        sd1[t] = fmaxf(a, 0.f);
    }
    __syncthreads();

    // 31 entries: warp w covers k2 [32w, 32w+32); lane < DU -> entry
    {
        float p = 0.f;
        if (lane < DU) {
            int u = bid * DU + lane;
            if (u < UTRI) {
                #pragma unroll 8
                for (int k2 = w * 32; k2 < w * 32 + 32; k2++)
                    p += sd1[k2] * Wd2[k2 * NUM_LOGITS + u];
            }
        }
        spart[w][lane] = p;
    }
    __syncthreads();
    if (t < DU) {
        int u = bid * DU + t;
        if (u < UTRI) {
            float a = bd2[u];
            #pragma unroll
            for (int w2 = 0; w2 < 8; w2++) a += spart[w2][t];
            int uu = u, rr = 0, rem = N - 1;
            while (uu >= rem) { uu -= rem; rem--; rr++; }
            int cc = rr + 1 + uu;
            float th  = tanhf(a);
            float sig = 1.f / (1.f + expf(-th));
            g_B[rr * N + cc] = sig;               // B IS symmetric
            g_B[cc * N + rr] = sig;
        }
    }
    if (bid == 0 && t < N) g_B[t * (N + 1)] = 1.f;   // diag = 1
}

// ============================= MPM KERNEL ==================================
// Startup computes B stats / nd locally. M0 never materialized (all rows
// identical). Gather: 16 fully-unrolled independent ldcg (zero-row padding)
// + rare dynamic tail -> one L2 latency exposure per iteration.
// F positively homogeneous: exact uniform rescale every 4 iters; final exact.
template <int CSZ>
__global__ void __launch_bounds__(NT2, 1)
mpm_k(float* __restrict__ out)
{
    constexpr int RPB = N / CSZ;
    constexpr int XE  = RPB * N;

    __shared__ __align__(16) float sX[XE];
    __shared__ float sND[XE];
    __shared__ float sdb[N];
    __shared__ float sm0[N];
    __shared__ int   snbroff[RPB * DMAX];
    __shared__ int   sdegp[RPB];          // padded degree (mult of 4)
    __shared__ int   sdegr[RPB];          // real degree
    __shared__ float red[24];

    const int t    = threadIdx.x;
    const int bid  = blockIdx.x;
    const int lane = t & 31, wid = t >> 5;
    const int q    = t >> 3;
    const int c    = t & 7;
    const int gbase = bid * XE;

    // ---- startup: B row stats (coalesced; B symmetric -> col stats) -------
    for (int row = wid; row < N; row += 24) {
        float b0 = g_B[row * N + lane];
        float b1 = g_B[row * N + lane + 32];
        float b2 = g_B[row * N + lane + 64];
        float s  = b0 + b1 + b2;
        float m  = fmaxf(fmaxf((lane == row) ? 0.f : b0,
                               (lane + 32 == row) ? 0.f : b1),
                               (lane + 64 == row) ? 0.f : b2);
        #pragma unroll
        for (int o = 16; o; o >>= 1) {
            s = s + __shfl_xor_sync(~0u, s, o);
            m = fmaxf(m, __shfl_xor_sync(~0u, m, o));
        }
        if (lane == 0) { sdb[row] = s; sm0[row] = m * (1.f / N); }
    }
    for (int e = t; e < RPB * DMAX; e += NT2) {
        int rw = e / DMAX, m = e % DMAX;
        int dg = g_deg[bid * RPB + rw];
        dg = (dg > DMAX) ? DMAX : dg;
        snbroff[e] = (m < dg) ? g_nbr[(bid * RPB + rw) * N + m] * N : NN;
        if (m == 0) { sdegp[rw] = (dg + 3) & ~3; sdegr[rw] = dg; }
    }
    if (t < N) { __stcg(&g_M[0][NN + t], 0.f); __stcg(&g_M[1][NN + t], 0.f); }
    float Breg[12];
    #pragma unroll
    for (int j = 0; j < 12; j++) {
        int l = 12 * c + j;
        Breg[j] = (l == q) ? 0.f : g_B[l * N + q];
    }
    __syncthreads();
    for (int e = t; e < XE; e += NT2) {
        int rw = e / 96;
        sX[e]  = 1.f / N;
        sND[e] = 1.f / (fabsf(g_degA[bid * RPB + rw] - sdb[e % 96]) + 1.f);
    }
    __syncthreads();

    for (int it = 0; it < ITERS; it++) {
        const float* __restrict__ Min  = g_M[it & 1];
        float*       __restrict__ Mout = g_M[(it + 1) & 1];

        float scale = 1.f;
        if (it > 0 && (it & 3) == 0) {
            float p = (lane < CSZ) ? __ldcg(&g_part[lane]) : 0.f;
            p += __shfl_xor_sync(~0u, p, 8);
            p += __shfl_xor_sync(~0u, p, 4);
            p += __shfl_xor_sync(~0u, p, 2);
            p += __shfl_xor_sync(~0u, p, 1);
            scale = rsqrtf(__shfl_sync(~0u, p, 0));
        }
        const bool last = (it == ITERS - 1);
        const bool pub  = ((it & 3) == 3) || last;

        float sq = 0.f;
        for (int e = t; e < XE; e += NT2) {
            int rw = e / 96, col = e % 96;
            float raw = sX[e] * sND[e];
            if (it == 0) {
                raw += (float)sdegr[rw] * sm0[col];   // all M0 rows identical
            } else {
                const int* off = &snbroff[rw * DMAX];
                // 16 independent loads (padding hits the zero row)
                float a0  = __ldcg(&Min[off[0]  + col]);
                float a1  = __ldcg(&Min[off[1]  + col]);
                float a2  = __ldcg(&Min[off[2]  + col]);
                float a3  = __ldcg(&Min[off[3]  + col]);
                float a4  = __ldcg(&Min[off[4]  + col]);
                float a5  = __ldcg(&Min[off[5]  + col]);
                float a6  = __ldcg(&Min[off[6]  + col]);
                float a7  = __ldcg(&Min[off[7]  + col]);
                float a8  = __ldcg(&Min[off[8]  + col]);
                float a9  = __ldcg(&Min[off[9]  + col]);
                float a10 = __ldcg(&Min[off[10] + col]);
                float a11 = __ldcg(&Min[off[11] + col]);
                float a12 = __ldcg(&Min[off[12] + col]);
                float a13 = __ldcg(&Min[off[13] + col]);
                float a14 = __ldcg(&Min[off[14] + col]);
                float a15 = __ldcg(&Min[off[15] + col]);
                raw += (((a0 + a1) + (a2 + a3)) + ((a4 + a5) + (a6 + a7)))
                     + (((a8 + a9) + (a10 + a11)) + ((a12 + a13) + (a14 + a15)));
                int dp = sdegp[rw];
                for (int m = 16; m < dp; m += 4) {   // rare tail (deg > 16)
                    raw += __ldcg(&Min[off[m]     + col])
                         + __ldcg(&Min[off[m + 1] + col])
                         + __ldcg(&Min[off[m + 2] + col])
                         + __ldcg(&Min[off[m + 3] + col]);
                }
            }
            float v = raw * scale;
            sX[e] = v;
            if (pub) sq += v * v;
        }
        if (pub) {
            #pragma unroll
            for (int o = 16; o; o >>= 1) sq += __shfl_xor_sync(~0u, sq, o);
            if (lane == 0) red[wid] = sq;
        }
        __syncthreads();
        if (pub && t == 0) {
            float s2 = 0.f;
            #pragma unroll
            for (int w = 0; w < 24; w++) s2 += red[w];
            __stcg(&g_part[bid], s2);
        }

        if (!last) {
            #pragma unroll
            for (int r2 = 0; r2 < RPB; r2++) {
                const float4* xp = (const float4*)&sX[r2 * N + 12 * c];
                float4 x0 = xp[0], x1 = xp[1], x2 = xp[2];
                float ma, mb;
                ma =           Breg[0]  * x0.x;  mb =           Breg[1]  * x0.y;
                ma = fmaxf(ma, Breg[2]  * x0.z); mb = fmaxf(mb, Breg[3]  * x0.w);
                ma = fmaxf(ma, Breg[4]  * x1.x); mb = fmaxf(mb, Breg[5]  * x1.y);
                ma = fmaxf(ma, Breg[6]  * x1.z); mb = fmaxf(mb, Breg[7]  * x1.w);
                ma = fmaxf(ma, Breg[8]  * x2.x); mb = fmaxf(mb, Breg[9]  * x2.y);
                ma = fmaxf(ma, Breg[10] * x2.z); mb = fmaxf(mb, Breg[11] * x2.w);
                float m = fmaxf(ma, mb);
                m = fmaxf(m, __shfl_down_sync(~0u, m, 4));
                m = fmaxf(m, __shfl_down_sync(~0u, m, 2));
                m = fmaxf(m, __shfl_down_sync(~0u, m, 1));
                if (c == 0) __stcg(&Mout[gbase + r2 * N + q], m);
            }
        }
        CSYNC();
    }

    // exact final normalization
    {
        float p = (lane < CSZ) ? __ldcg(&g_part[lane]) : 0.f;
        p += __shfl_xor_sync(~0u, p, 8);
        p += __shfl_xor_sync(~0u, p, 4);
        p += __shfl_xor_sync(~0u, p, 2);
        p += __shfl_xor_sync(~0u, p, 1);
        float os = rsqrtf(__shfl_sync(~0u, p, 0));
        for (int e = t; e < XE; e += NT2)
            out[gbase + e] = sX[e] * os;
    }
}

// ---------------- launch ----------------
extern "C" void kernel_launch(void* const* d_in, const int* in_sizes, int n_in,
                              void* d_out, int out_size) {
    const float* x   = (const float*)d_in[0];
    const int*   ei  = (const int*)  d_in[1];
    const float* adj = (const float*)d_in[2];
    const float* W1  = (const float*)d_in[3];
    // d_in[4] = b1 (cancelled by BN)
    const float* g1  = (const float*)d_in[5];
    const float* be1 = (const float*)d_in[6];
    const float* W2  = (const float*)d_in[7];
    // d_in[8] = b2 (cancelled by BN)
    const float* g2  = (const float*)d_in[9];
    const float* be2 = (const float*)d_in[10];
    const float* Wmu = (const float*)d_in[11];
    const float* bmu = (const float*)d_in[12];
    const float* Wlv = (const float*)d_in[13];
    const float* blv = (const float*)d_in[14];
    const float* Wd1 = (const float*)d_in[15];
    const float* bd1 = (const float*)d_in[16];
    const float* Wd2 = (const float*)d_in[17];
    const float* bd2 = (const float*)d_in[18];
    const float* eps = (const float*)d_in[19];
    float* o = (float*)d_out;

    const size_t sh16 = (size_t)(N * ATS + 2 * 96 * 17) * sizeof(float);
    const size_t sh8  = (size_t)(N * ATS + 2 * 96 * 33) * sizeof(float);

    cudaFuncSetAttribute(prologue_k<16>, cudaFuncAttributeNonPortableClusterSizeAllowed, 1);
    cudaFuncSetAttribute(mpm_k<16>,      cudaFuncAttributeNonPortableClusterSizeAllowed, 1);
    cudaFuncSetAttribute(prologue_k<16>, cudaFuncAttributeMaxDynamicSharedMemorySize, (int)sh16);
    cudaFuncSetAttribute(prologue_k<8>,  cudaFuncAttributeMaxDynamicSharedMemorySize, (int)sh8);

    cudaLaunchAttribute at16[1];
    at16[0].id = cudaLaunchAttributeClusterDimension;
    at16[0].val.clusterDim = {16, 1, 1};

    cudaLaunchConfig_t cfgP16 = {};
    cfgP16.gridDim = dim3(16, 1, 1);
    cfgP16.blockDim = dim3(NT, 1, 1);
    cfgP16.dynamicSmemBytes = sh16;
    cfgP16.attrs = at16;  cfgP16.numAttrs = 1;

    cudaLaunchConfig_t cfgM16 = {};
    cfgM16.gridDim = dim3(16, 1, 1);
    cfgM16.blockDim = dim3(NT2, 1, 1);
    cfgM16.attrs = at16;  cfgM16.numAttrs = 1;

    int np = 0, nm = 0;
    cudaError_t e1 = cudaOccupancyMaxActiveClusters(&np, prologue_k<16>, &cfgP16);
    cudaError_t e2 = cudaOccupancyMaxActiveClusters(&nm, mpm_k<16>, &cfgM16);
    if (e1 != cudaSuccess || e2 != cudaSuccess) { (void)cudaGetLastError(); np = nm = 0; }

    if (np >= 1 && nm >= 1) {
        cudaLaunchKernelEx(&cfgP16, prologue_k<16>,
            x, ei, W1, g1, be1, W2, g2, be2);
        decoder_k<<<NDEC, 256>>>(adj, Wmu, bmu, Wlv, blv, Wd1, bd1, Wd2, bd2, eps);
        cudaLaunchKernelEx(&cfgM16, mpm_k<16>, o);
    } else {
        cudaLaunchAttribute at8[1];
        at8[0].id = cudaLaunchAttributeClusterDimension;
        at8[0].val.clusterDim = {8, 1, 1};
        cudaLaunchConfig_t cfgP8 = {};
        cfgP8.gridDim = dim3(8, 1, 1);
        cfgP8.blockDim = dim3(NT, 1, 1);
        cfgP8.dynamicSmemBytes = sh8;
        cfgP8.attrs = at8;  cfgP8.numAttrs = 1;
        cudaLaunchConfig_t cfgM8 = {};
        cfgM8.gridDim = dim3(8, 1, 1);
        cfgM8.blockDim = dim3(NT2, 1, 1);
        cfgM8.attrs = at8;  cfgM8.numAttrs = 1;
        cudaLaunchKernelEx(&cfgP8, prologue_k<8>,
            x, ei, W1, g1, be1, W2, g2, be2);
        decoder_k<<<NDEC, 256>>>(adj, Wmu, bmu, Wlv, blv, Wd1, bd1, Wd2, bd2, eps);
        cudaLaunchKernelEx(&cfgM8, mpm_k<8>, o);
    }
}

// round 16
// speedup vs baseline: 1.8202x; 1.0219x over previous
#include <cuda_runtime.h>
#include <math.h>

#define N        96
#define NT       384     // prologue threads per CTA
#define NT2      768     // MPM threads per CTA (24 warps)
#define NDEC     148     // decoder CTAs (one full wave); 148*31 >= UTRI
#define DU       31      // upper-tri entries per decoder CTA
#define NN       9216
#define ATS      97      // padded stride for transposed matrices in smem
#define IN_DIM   64
#define HID      256
#define ZD       64
#define E        1024
#define NUM_LOGITS 4656
#define ITERS    50
#define UTRI     4560
#define DMAX     32      // padded neighbor-list capacity

#define PREF_L2(p) asm volatile("prefetch.global.L2 [%0];" :: "l"(p))

// ---------------- device scratch (no allocations allowed) ----------------
__device__ float g_Ht[N * HID];       // layer-1 activations, TRANSPOSED
__device__ float g_gv[HID];
__device__ float g_B[NN];
__device__ float g_degA[N];
__device__ int   g_deg[N];
__device__ int   g_nbr[NN];
__device__ float g_M[2][NN + N];      // +1 zero row for padded neighbors
__device__ float g_part[16];          // per-CTA sum-of-squares partials

#define C_ARRIVE() asm volatile("barrier.cluster.arrive.aligned;" ::: "memory")
#define C_WAIT()   asm volatile("barrier.cluster.wait.aligned;"   ::: "memory")
#define CSYNC() do { C_ARRIVE(); C_WAIT(); } while (0)

// =========================== PROLOGUE KERNEL ===============================
// GCN-only, ONE cluster sync. Every CTA redundantly builds A_norm^T in its
// own smem from edge_index (directed! A_norm is NOT symmetric) — removes the
// CTA0 serialization and the g_Anorm global round-trip entirely.
template <int CSZ>
__global__ void __launch_bounds__(NT, 1)
prologue_k(
    const float* __restrict__ x,   const int* __restrict__ ei,
    const float* __restrict__ W1,  const float* __restrict__ g1,  const float* __restrict__ be1,
    const float* __restrict__ W2,  const float* __restrict__ g2,  const float* __restrict__ be2)
{
    constexpr int CPC = HID / CSZ;     // 16 (or 32)
    constexpr int CW  = CPC / 4;
    constexpr int STP = CPC + 1;

    extern __shared__ float sm[];
    float* At = sm;                    // 96*ATS: At[c*ATS+r] = A_norm[r][c]
    float* xs = sm + N * ATS;          // 64*ATS: x^T staged
    float* sT = xs + IN_DIM * ATS;     // 96*STP
    float* sP = sT + 96 * STP;         // 96*STP

    __shared__ float stmp[N];

    const int t    = threadIdx.x;
    const int bid  = blockIdx.x;
    const int lane = t & 31, wid = t >> 5;
    const int r    = t % 96, g = t / 96;
    const int lc   = g * CW;
    const int gcol = bid * CPC + lc;

    // ---- warm L2 with this CTA's weight slices (fire-and-forget) ---------
    if (t < IN_DIM) PREF_L2(&W1[t * HID + bid * CPC]);
    if (t < HID)    PREF_L2(&W2[t * HID + bid * CPC]);

    // ---- build A_norm^T locally (replicated; ~1us) ------------------------
    for (int i = t; i < N * ATS; i += NT) At[i] = 0.f;
    __syncthreads();
    for (int e = t; e < E; e += NT) {
        int s = ei[e], d = ei[E + e];
        At[d * ATS + s] = 1.f;                    // A[s][d]=1 (identical-value races OK)
    }
    if (t < N) At[t * ATS + t] = 1.f;             // A = max(A, I) (same-value race OK)
    // stage x^T concurrently (disjoint smem region)
    for (int i = t; i < N * IN_DIM; i += NT) {
        int rr = i >> 6, k = i & 63;
        xs[k * ATS + rr] = x[i];
    }
    __syncthreads();
    if (t < N) {                                  // row sums of A (axis 1)
        float s = 0.f;
        #pragma unroll 4
        for (int d = 0; d < N; d++) s += At[d * ATS + t];
        stmp[t] = rsqrtf(s);
    }
    __syncthreads();
    for (int e = t; e < NN; e += NT) {            // A_norm = A*dinv_r*dinv_c
        int cc = e / N, rr = e - cc * N;
        At[cc * ATS + rr] *= stmp[rr] * stmp[cc];
    }
    // gemm1 (independent of At normalize; sync below covers both)
    {
        float acc[CW];
        #pragma unroll
        for (int c = 0; c < CW; c++) acc[c] = 0.f;
        #pragma unroll 8
        for (int k = 0; k < IN_DIM; k++) {
            float xv = xs[k * ATS + r];
            #pragma unroll
            for (int c4 = 0; c4 < CW / 4; c4++) {
                float4 w = *(const float4*)&W1[k * HID + gcol + 4 * c4];
                acc[4*c4+0] += xv * w.x; acc[4*c4+1] += xv * w.y;
                acc[4*c4+2] += xv * w.z; acc[4*c4+3] += xv * w.w;
            }
        }
        #pragma unroll
        for (int c = 0; c < CW; c++) sT[r * STP + lc + c] = acc[c];
    }
    __syncthreads();

    auto gcnbn = [&](const float* gamma, const float* beta, bool writeH, bool dogv) {
        float acc[CW];
        #pragma unroll
        for (int c = 0; c < CW; c++) acc[c] = 0.f;
        #pragma unroll 4
        for (int j = 0; j < N; j++) {
            float a = At[j * ATS + r];            // A_norm[r][j] (true row)
            #pragma unroll
            for (int c = 0; c < CW; c++)
                acc[c] += a * sT[j * STP + lc + c];
        }
        #pragma unroll
        for (int c = 0; c < CW; c++) sP[r * STP + lc + c] = acc[c];
        __syncthreads();
        for (int cc = wid; cc < CPC; cc += 12) {  // warp-per-column BN
            int col = bid * CPC + cc;
            float v0 = sP[lane * STP + cc];
            float v1 = sP[(lane + 32) * STP + cc];
            float v2 = sP[(lane + 64) * STP + cc];
            float s = v0 + v1 + v2, qd = v0*v0 + v1*v1 + v2*v2;
            #pragma unroll
            for (int o = 16; o; o >>= 1) {
                s  += __shfl_xor_sync(~0u, s, o);
                qd += __shfl_xor_sync(~0u, qd, o);
            }
            float m   = s * (1.f / N);
            float var = qd * (1.f / N) - m * m;
            float inv = rsqrtf(var + 1e-5f) * gamma[col];
            float bb  = beta[col];
            float h0 = fmaxf((v0 - m) * inv + bb, 0.f);
            float h1 = fmaxf((v1 - m) * inv + bb, 0.f);
            float h2 = fmaxf((v2 - m) * inv + bb, 0.f);
            if (writeH) {                          // transposed -> coalesced
                g_Ht[col * 96 + lane]      = h0;
                g_Ht[col * 96 + lane + 32] = h1;
                g_Ht[col * 96 + lane + 64] = h2;
            }
            if (dogv) {
                float gs = h0 + h1 + h2;
                #pragma unroll
                for (int o = 16; o; o >>= 1) gs += __shfl_xor_sync(~0u, gs, o);
                if (lane == 0) g_gv[col] = gs * (1.f / N);
            }
        }
    };

    gcnbn(g1, be1, true, false);     // layer 1 -> g_Ht
    CSYNC();                         // the ONLY cluster sync: g_Ht exchange

    {   // gemm2: T = H @ W2 (W2 slice L2-warm)
        float acc[CW];
        #pragma unroll
        for (int c = 0; c < CW; c++) acc[c] = 0.f;
        #pragma unroll 8
        for (int k = 0; k < HID; k++) {
            float hv = g_Ht[k * 96 + r];
            #pragma unroll
            for (int c4 = 0; c4 < CW / 4; c4++) {
                float4 w = *(const float4*)&W2[k * HID + gcol + 4 * c4];
                acc[4*c4+0] += hv * w.x; acc[4*c4+1] += hv * w.y;
                acc[4*c4+2] += hv * w.z; acc[4*c4+3] += hv * w.w;
            }
        }
        __syncthreads();
        #pragma unroll
        for (int c = 0; c < CW; c++) sT[r * STP + lc + c] = acc[c];
    }
    __syncthreads();
    gcnbn(g2, be2, false, true);     // layer 2 -> g_gv (kernel end = sync)
}

// ============================ DECODER KERNEL ===============================
// Full-chip grid (148 CTAs, one wave, no cluster). Each CTA redundantly
// computes the VAE head and 31 upper-tri B entries. CTA 147 (3 entries only)
// also builds the adj_gt neighbor CSR (ballot compaction) for mpm_k.
__global__ void __launch_bounds__(256, 1)
decoder_k(const float* __restrict__ adj,
          const float* __restrict__ Wmu, const float* __restrict__ bmu,
          const float* __restrict__ Wlv, const float* __restrict__ blv,
          const float* __restrict__ Wd1, const float* __restrict__ bd1,
          const float* __restrict__ Wd2, const float* __restrict__ bd2,
          const float* __restrict__ eps)
{
    __shared__ float sgv[HID];
    __shared__ float sz[ZD];
    __shared__ float sd1[HID];
    __shared__ float smu[4][ZD], slv[4][ZD];
    __shared__ float spart[8][32];

    const int t   = threadIdx.x;
    const int bid = blockIdx.x;
    const int w   = t >> 5, lane = t & 31;

    // warm L2 with this CTA's Wd2 columns (124B per k2 row)
    {
        const float* p = &Wd2[t * NUM_LOGITS + bid * DU];
        PREF_L2(p);
        PREF_L2(p + 24);
    }

    // CTA 147: build neighbor CSR from adj_gt (warp ballot compaction)
    if (bid == NDEC - 1) {
        for (int r = w; r < N; r += 8) {
            float a0 = adj[r * N + lane];
            float a1 = adj[r * N + 32 + lane];
            float a2 = adj[r * N + 64 + lane];
            unsigned m0 = __ballot_sync(~0u, a0 > 0.5f);
            unsigned m1 = __ballot_sync(~0u, a1 > 0.5f);
            unsigned m2 = __ballot_sync(~0u, a2 > 0.5f);
            int c0 = __popc(m0), c1 = __popc(m1);
            unsigned lt = (1u << lane) - 1u;
            if (a0 > 0.5f) g_nbr[r * N + __popc(m0 & lt)] = lane;
            if (a1 > 0.5f) g_nbr[r * N + c0 + __popc(m1 & lt)] = lane + 32;
            if (a2 > 0.5f) g_nbr[r * N + c0 + c1 + __popc(m2 & lt)] = lane + 64;
            if (lane == 0) {
                int dg = c0 + c1 + __popc(m2);
                g_deg[r]  = dg;
                g_degA[r] = (float)dg + 1.f;      // Agt diag forced to 1
            }
        }
    }

    sgv[t] = g_gv[t];
    __syncthreads();

    // mu/lv: 4-way k-split
    {
        int gg = t >> 6, cI = t & 63;
        float pm = 0.f, pl = 0.f;
        #pragma unroll 8
        for (int k = gg * 64; k < gg * 64 + 64; k++) {
            float gv = sgv[k];
            pm += gv * Wmu[k * ZD + cI];
            pl += gv * Wlv[k * ZD + cI];
        }
        smu[gg][cI] = pm; slv[gg][cI] = pl;
    }
    __syncthreads();
    if (t < ZD) {
        float mu = bmu[t] + smu[0][t] + smu[1][t] + smu[2][t] + smu[3][t];
        float lv = blv[t] + slv[0][t] + slv[1][t] + slv[2][t] + slv[3][t];
        lv = fminf(fmaxf(lv, -4.f), 4.f);
        sz[t] = mu + eps[t] * expf(0.5f * lv);
    }
    __syncthreads();
    {   // d1 = relu(z @ Wd1 + bd1)
        float a = bd1[t];
        #pragma unroll 8
        for (int d = 0; d < ZD; d++) a += sz[d] * Wd1[d * HID + t];
        sd1[t] = fmaxf(a, 0.f);
    }
    __syncthreads();

    // 31 entries: warp w covers k2 [32w, 32w+32); lane < DU -> entry
    {
        float p = 0.f;
        if (lane < DU) {
            int u = bid * DU + lane;
            if (u < UTRI) {
                #pragma unroll 8
                for (int k2 = w * 32; k2 < w * 32 + 32; k2++)
                    p += sd1[k2] * Wd2[k2 * NUM_LOGITS + u];
            }
        }
        spart[w][lane] = p;
    }
    __syncthreads();
    if (t < DU) {
        int u = bid * DU + t;
        if (u < UTRI) {
            float a = bd2[u];
            #pragma unroll
            for (int w2 = 0; w2 < 8; w2++) a += spart[w2][t];
            int uu = u, rr = 0, rem = N - 1;
            while (uu >= rem) { uu -= rem; rem--; rr++; }
            int cc = rr + 1 + uu;
            float th  = tanhf(a);
            float sig = 1.f / (1.f + expf(-th));
            g_B[rr * N + cc] = sig;               // B IS symmetric
            g_B[cc * N + rr] = sig;
        }
    }
    if (bid == 0 && t < N) g_B[t * (N + 1)] = 1.f;   // diag = 1
}

// ============================= MPM KERNEL ==================================
// Startup computes B stats / nd locally. M0 never materialized (all rows
// identical). Gather: 16 fully-unrolled independent ldcg (zero-row padding)
// + rare dynamic tail -> one L2 latency exposure per iteration.
// F positively homogeneous: exact uniform rescale every 4 iters; final exact.
template <int CSZ>
__global__ void __launch_bounds__(NT2, 1)
mpm_k(float* __restrict__ out)
{
    constexpr int RPB = N / CSZ;
    constexpr int XE  = RPB * N;

    __shared__ __align__(16) float sX[XE];
    __shared__ float sND[XE];
    __shared__ float sdb[N];
    __shared__ float sm0[N];
    __shared__ int   snbroff[RPB * DMAX];
    __shared__ int   sdegp[RPB];          // padded degree (mult of 4)
    __shared__ int   sdegr[RPB];          // real degree
    __shared__ float red[24];

    const int t    = threadIdx.x;
    const int bid  = blockIdx.x;
    const int lane = t & 31, wid = t >> 5;
    const int q    = t >> 3;
    const int c    = t & 7;
    const int gbase = bid * XE;

    // ---- startup: B row stats (coalesced; B symmetric -> col stats) -------
    for (int row = wid; row < N; row += 24) {
        float b0 = g_B[row * N + lane];
        float b1 = g_B[row * N + lane + 32];
        float b2 = g_B[row * N + lane + 64];
        float s  = b0 + b1 + b2;
        float m  = fmaxf(fmaxf((lane == row) ? 0.f : b0,
                               (lane + 32 == row) ? 0.f : b1),
                               (lane + 64 == row) ? 0.f : b2);
        #pragma unroll
        for (int o = 16; o; o >>= 1) {
            s = s + __shfl_xor_sync(~0u, s, o);
            m = fmaxf(m, __shfl_xor_sync(~0u, m, o));
        }
        if (lane == 0) { sdb[row] = s; sm0[row] = m * (1.f / N); }
    }
    for (int e = t; e < RPB * DMAX; e += NT2) {
        int rw = e / DMAX, m = e % DMAX;
        int dg = g_deg[bid * RPB + rw];
        dg = (dg > DMAX) ? DMAX : dg;
        snbroff[e] = (m < dg) ? g_nbr[(bid * RPB + rw) * N + m] * N : NN;
        if (m == 0) { sdegp[rw] = (dg + 3) & ~3; sdegr[rw] = dg; }
    }
    if (t < N) { __stcg(&g_M[0][NN + t], 0.f); __stcg(&g_M[1][NN + t], 0.f); }
    float Breg[12];
    #pragma unroll
    for (int j = 0; j < 12; j++) {
        int l = 12 * c + j;
        Breg[j] = (l == q) ? 0.f : g_B[l * N + q];
    }
    __syncthreads();
    for (int e = t; e < XE; e += NT2) {
        int rw = e / 96;
        sX[e]  = 1.f / N;
        sND[e] = 1.f / (fabsf(g_degA[bid * RPB + rw] - sdb[e % 96]) + 1.f);
    }
    __syncthreads();

    for (int it = 0; it < ITERS; it++) {
        const float* __restrict__ Min  = g_M[it & 1];
        float*       __restrict__ Mout = g_M[(it + 1) & 1];

        float scale = 1.f;
        if (it > 0 && (it & 3) == 0) {
            float p = (lane < CSZ) ? __ldcg(&g_part[lane]) : 0.f;
            p += __shfl_xor_sync(~0u, p, 8);
            p += __shfl_xor_sync(~0u, p, 4);
            p += __shfl_xor_sync(~0u, p, 2);
            p += __shfl_xor_sync(~0u, p, 1);
            scale = rsqrtf(__shfl_sync(~0u, p, 0));
        }
        const bool last = (it == ITERS - 1);
        const bool pub  = ((it & 3) == 3) || last;

        float sq = 0.f;
        for (int e = t; e < XE; e += NT2) {
            int rw = e / 96, col = e % 96;
            float raw = sX[e] * sND[e];
            if (it == 0) {
                raw += (float)sdegr[rw] * sm0[col];   // all M0 rows identical
            } else {
                const int* off = &snbroff[rw * DMAX];
                // 16 independent loads (padding hits the zero row)
                float a0  = __ldcg(&Min[off[0]  + col]);
                float a1  = __ldcg(&Min[off[1]  + col]);
                float a2  = __ldcg(&Min[off[2]  + col]);
                float a3  = __ldcg(&Min[off[3]  + col]);
                float a4  = __ldcg(&Min[off[4]  + col]);
                float a5  = __ldcg(&Min[off[5]  + col]);
                float a6  = __ldcg(&Min[off[6]  + col]);
                float a7  = __ldcg(&Min[off[7]  + col]);
                float a8  = __ldcg(&Min[off[8]  + col]);
                float a9  = __ldcg(&Min[off[9]  + col]);
                float a10 = __ldcg(&Min[off[10] + col]);
                float a11 = __ldcg(&Min[off[11] + col]);
                float a12 = __ldcg(&Min[off[12] + col]);
                float a13 = __ldcg(&Min[off[13] + col]);
                float a14 = __ldcg(&Min[off[14] + col]);
                float a15 = __ldcg(&Min[off[15] + col]);
                raw += (((a0 + a1) + (a2 + a3)) + ((a4 + a5) + (a6 + a7)))
                     + (((a8 + a9) + (a10 + a11)) + ((a12 + a13) + (a14 + a15)));
                int dp = sdegp[rw];
                for (int m = 16; m < dp; m += 4) {   // rare tail (deg > 16)
                    raw += __ldcg(&Min[off[m]     + col])
                         + __ldcg(&Min[off[m + 1] + col])
                         + __ldcg(&Min[off[m + 2] + col])
                         + __ldcg(&Min[off[m + 3] + col]);
                }
            }
            float v = raw * scale;
            sX[e] = v;
            if (pub) sq += v * v;
        }
        if (pub) {
            #pragma unroll
            for (int o = 16; o; o >>= 1) sq += __shfl_xor_sync(~0u, sq, o);
            if (lane == 0) red[wid] = sq;
        }
        __syncthreads();
        if (pub && t == 0) {
            float s2 = 0.f;
            #pragma unroll
            for (int w = 0; w < 24; w++) s2 += red[w];
            __stcg(&g_part[bid], s2);
        }

        if (!last) {
            #pragma unroll
            for (int r2 = 0; r2 < RPB; r2++) {
                const float4* xp = (const float4*)&sX[r2 * N + 12 * c];
                float4 x0 = xp[0], x1 = xp[1], x2 = xp[2];
                float ma, mb;
                ma =           Breg[0]  * x0.x;  mb =           Breg[1]  * x0.y;
                ma = fmaxf(ma, Breg[2]  * x0.z); mb = fmaxf(mb, Breg[3]  * x0.w);
                ma = fmaxf(ma, Breg[4]  * x1.x); mb = fmaxf(mb, Breg[5]  * x1.y);
                ma = fmaxf(ma, Breg[6]  * x1.z); mb = fmaxf(mb, Breg[7]  * x1.w);
                ma = fmaxf(ma, Breg[8]  * x2.x); mb = fmaxf(mb, Breg[9]  * x2.y);
                ma = fmaxf(ma, Breg[10] * x2.z); mb = fmaxf(mb, Breg[11] * x2.w);
                float m = fmaxf(ma, mb);
                m = fmaxf(m, __shfl_down_sync(~0u, m, 4));
                m = fmaxf(m, __shfl_down_sync(~0u, m, 2));
                m = fmaxf(m, __shfl_down_sync(~0u, m, 1));
                if (c == 0) __stcg(&Mout[gbase + r2 * N + q], m);
            }
        }
        CSYNC();
    }

    // exact final normalization
    {
        float p = (lane < CSZ) ? __ldcg(&g_part[lane]) : 0.f;
        p += __shfl_xor_sync(~0u, p, 8);
        p += __shfl_xor_sync(~0u, p, 4);
        p += __shfl_xor_sync(~0u, p, 2);
        p += __shfl_xor_sync(~0u, p, 1);
        float os = rsqrtf(__shfl_sync(~0u, p, 0));
        for (int e = t; e < XE; e += NT2)
            out[gbase + e] = sX[e] * os;
    }
}

// ---------------- launch ----------------
extern "C" void kernel_launch(void* const* d_in, const int* in_sizes, int n_in,
                              void* d_out, int out_size) {
    const float* x   = (const float*)d_in[0];
    const int*   ei  = (const int*)  d_in[1];
    const float* adj = (const float*)d_in[2];
    const float* W1  = (const float*)d_in[3];
    // d_in[4] = b1 (cancelled by BN)
    const float* g1  = (const float*)d_in[5];
    const float* be1 = (const float*)d_in[6];
    const float* W2  = (const float*)d_in[7];
    // d_in[8] = b2 (cancelled by BN)
    const float* g2  = (const float*)d_in[9];
    const float* be2 = (const float*)d_in[10];
    const float* Wmu = (const float*)d_in[11];
    const float* bmu = (const float*)d_in[12];
    const float* Wlv = (const float*)d_in[13];
    const float* blv = (const float*)d_in[14];
    const float* Wd1 = (const float*)d_in[15];
    const float* bd1 = (const float*)d_in[16];
    const float* Wd2 = (const float*)d_in[17];
    const float* bd2 = (const float*)d_in[18];
    const float* eps = (const float*)d_in[19];
    float* o = (float*)d_out;

    // smem: A_norm^T (96*97) + x^T (64*97) + sT/sP (2*96*STP)
    const size_t sh16 = (size_t)((N + IN_DIM) * ATS + 2 * 96 * 17) * sizeof(float);
    const size_t sh8  = (size_t)((N + IN_DIM) * ATS + 2 * 96 * 33) * sizeof(float);

    cudaFuncSetAttribute(prologue_k<16>, cudaFuncAttributeNonPortableClusterSizeAllowed, 1);
    cudaFuncSetAttribute(mpm_k<16>,      cudaFuncAttributeNonPortableClusterSizeAllowed, 1);
    cudaFuncSetAttribute(prologue_k<16>, cudaFuncAttributeMaxDynamicSharedMemorySize, (int)sh16);
    cudaFuncSetAttribute(prologue_k<8>,  cudaFuncAttributeMaxDynamicSharedMemorySize, (int)sh8);

    cudaLaunchAttribute at16[1];
    at16[0].id = cudaLaunchAttributeClusterDimension;
    at16[0].val.clusterDim = {16, 1, 1};

    cudaLaunchConfig_t cfgP16 = {};
    cfgP16.gridDim = dim3(16, 1, 1);
    cfgP16.blockDim = dim3(NT, 1, 1);
    cfgP16.dynamicSmemBytes = sh16;
    cfgP16.attrs = at16;  cfgP16.numAttrs = 1;

    cudaLaunchConfig_t cfgM16 = {};
    cfgM16.gridDim = dim3(16, 1, 1);
    cfgM16.blockDim = dim3(NT2, 1, 1);
    cfgM16.attrs = at16;  cfgM16.numAttrs = 1;

    int np = 0, nm = 0;
    cudaError_t e1 = cudaOccupancyMaxActiveClusters(&np, prologue_k<16>, &cfgP16);
    cudaError_t e2 = cudaOccupancyMaxActiveClusters(&nm, mpm_k<16>, &cfgM16);
    if (e1 != cudaSuccess || e2 != cudaSuccess) { (void)cudaGetLastError(); np = nm = 0; }

    if (np >= 1 && nm >= 1) {
        cudaLaunchKernelEx(&cfgP16, prologue_k<16>,
            x, ei, W1, g1, be1, W2, g2, be2);
        decoder_k<<<NDEC, 256>>>(adj, Wmu, bmu, Wlv, blv, Wd1, bd1, Wd2, bd2, eps);
        cudaLaunchKernelEx(&cfgM16, mpm_k<16>, o);
    } else {
        cudaLaunchAttribute at8[1];
        at8[0].id = cudaLaunchAttributeClusterDimension;
        at8[0].val.clusterDim = {8, 1, 1};
        cudaLaunchConfig_t cfgP8 = {};
        cfgP8.gridDim = dim3(8, 1, 1);
        cfgP8.blockDim = dim3(NT, 1, 1);
        cfgP8.dynamicSmemBytes = sh8;
        cfgP8.attrs = at8;  cfgP8.numAttrs = 1;
        cudaLaunchConfig_t cfgM8 = {};
        cfgM8.gridDim = dim3(8, 1, 1);
        cfgM8.blockDim = dim3(NT2, 1, 1);
        cfgM8.attrs = at8;  cfgM8.numAttrs = 1;
        cudaLaunchKernelEx(&cfgP8, prologue_k<8>,
            x, ei, W1, g1, be1, W2, g2, be2);
        decoder_k<<<NDEC, 256>>>(adj, Wmu, bmu, Wlv, blv, Wd1, bd1, Wd2, bd2, eps);
        cudaLaunchKernelEx(&cfgM8, mpm_k<8>, o);
    }
}